// round 1
// baseline (speedup 1.0000x reference)
#include <cuda_runtime.h>

// Problem constants
#define B_DIM   4
#define S_DIM   4096
#define H_DIM   4096
#define HD      512
#define ROPE_D  64
#define RATIO   4
#define C_DIM   (S_DIM / RATIO)          // 1024
#define M_TOT   (B_DIM * S_DIM)          // 16384
#define K_TOT   H_DIM                    // 4096
#define N_KV    (2 * HD)                 // 1024

// Scratch (device globals — no allocations allowed in kernel_launch)
__device__ __align__(16) float g_kvg[(size_t)M_TOT * N_KV];  // gated kv, 64 MiB
__device__ __align__(16) float g_w8[8 * HD];
__device__ __align__(16) float g_w0[4 * HD];

// ---------------------------------------------------------------------------
// Packed fp32x2 FMA (Blackwell sm_10x): 2 FMAs per issue slot on the fma pipe
// ---------------------------------------------------------------------------
__device__ __forceinline__ unsigned long long fma2(unsigned long long a,
                                                   unsigned long long b,
                                                   unsigned long long c) {
    unsigned long long d;
    asm("fma.rn.f32x2 %0, %1, %2, %3;" : "=l"(d) : "l"(a), "l"(b), "l"(c));
    return d;
}
__device__ __forceinline__ float2 unpack2(unsigned long long v) {
    float2 r;
    asm("mov.b64 {%0, %1}, %2;" : "=f"(r.x), "=f"(r.y) : "l"(v));
    return r;
}

// ---------------------------------------------------------------------------
// Kernel 1: softmax weights from ape (tiny)
//   ape: (4, 1024) row-major.
//   w8[i][d] = softmax over i of concat(ape[:, :512], ape[:, 512:]) (8 rows)
//   w0[r][d] = softmax over r of ape[:, :512] (4 rows)
// ---------------------------------------------------------------------------
__global__ void weights_kernel(const float* __restrict__ ape) {
    int d = threadIdx.x;  // 0..511
    float v[8];
#pragma unroll
    for (int r = 0; r < 4; r++) {
        v[r]     = ape[r * 1024 + d];
        v[4 + r] = ape[r * 1024 + 512 + d];
    }
    // w0 over v[0..3]
    float m4 = v[0];
#pragma unroll
    for (int i = 1; i < 4; i++) m4 = fmaxf(m4, v[i]);
    float e4[4];
    float s4 = 0.f;
#pragma unroll
    for (int i = 0; i < 4; i++) { e4[i] = expf(v[i] - m4); s4 += e4[i]; }
    float inv4 = 1.f / s4;
#pragma unroll
    for (int i = 0; i < 4; i++) g_w0[i * HD + d] = e4[i] * inv4;
    // w8 over v[0..7]
    float m8 = v[0];
#pragma unroll
    for (int i = 1; i < 8; i++) m8 = fmaxf(m8, v[i]);
    float e8[8];
    float s8 = 0.f;
#pragma unroll
    for (int i = 0; i < 8; i++) { e8[i] = expf(v[i] - m8); s8 += e8[i]; }
    float inv8 = 1.f / s8;
#pragma unroll
    for (int i = 0; i < 8; i++) g_w8[i * HD + d] = e8[i] * inv8;
}

// ---------------------------------------------------------------------------
// Kernel 2: fused dual GEMM + sigmoid gating.
//   Y_kv = X @ W_kv^T,  Y_g = X @ W_gate^T,  g_kvg = Y_kv * sigmoid(Y_g)
//   X: (16384, 4096), W_*: (1024, 4096), both K-contiguous.
//   Tile: BM=128, BN=64 (both matrices), BK=16; 256 threads; per-thread 8x4
//   accumulators for each matrix, as fp32x2 pairs along N.
//   A is stored DUPLICATED in SMEM so the broadcast operand of fma.rn.f32x2
//   loads directly as a packed {a,a} pair (no per-k register packing).
// ---------------------------------------------------------------------------
__global__ void __launch_bounds__(256) gemm_kernel(const float* __restrict__ X,
                                                   const float* __restrict__ Wkv,
                                                   const float* __restrict__ Wg) {
    __shared__ __align__(16) float As[16][256];   // duplicated A: As[k][2m]=As[k][2m+1]=A[m][k]
    __shared__ __align__(16) float Bks[16][64];
    __shared__ __align__(16) float Bgs[16][64];

    const int t  = threadIdx.x;
    const int tx = t & 15;       // n-group: cols tx*4 .. tx*4+3
    const int ty = t >> 4;       // m-group: rows ty*8 .. ty*8+7
    const int n0 = blockIdx.x * 64;
    const int m0 = blockIdx.y * 128;

    const int rowL = t >> 2;     // 0..63
    const int kq   = t & 3;

    const float* Abase0 = X   + (size_t)(m0 + rowL)      * K_TOT + kq * 4;
    const float* Abase1 = X   + (size_t)(m0 + rowL + 64) * K_TOT + kq * 4;
    const float* Bkbase = Wkv + (size_t)(n0 + rowL)      * K_TOT + kq * 4;
    const float* Bgbase = Wg  + (size_t)(n0 + rowL)      * K_TOT + kq * 4;

    unsigned long long acc_kv[8][2];
    unsigned long long acc_g[8][2];
#pragma unroll
    for (int i = 0; i < 8; i++) {
        acc_kv[i][0] = 0ULL; acc_kv[i][1] = 0ULL;
        acc_g[i][0]  = 0ULL; acc_g[i][1]  = 0ULL;
    }

    for (int k0 = 0; k0 < K_TOT; k0 += 16) {
        float4 a0 = *(const float4*)(Abase0 + k0);
        float4 a1 = *(const float4*)(Abase1 + k0);
        float4 bk = *(const float4*)(Bkbase + k0);
        float4 bg = *(const float4*)(Bgbase + k0);
        __syncthreads();  // previous tile's compute done before overwrite
        {
            const int kk = kq * 4;
            const int r0 = 2 * rowL;
            const int r1 = 2 * (rowL + 64);
            As[kk + 0][r0] = a0.x; As[kk + 0][r0 + 1] = a0.x;
            As[kk + 1][r0] = a0.y; As[kk + 1][r0 + 1] = a0.y;
            As[kk + 2][r0] = a0.z; As[kk + 2][r0 + 1] = a0.z;
            As[kk + 3][r0] = a0.w; As[kk + 3][r0 + 1] = a0.w;
            As[kk + 0][r1] = a1.x; As[kk + 0][r1 + 1] = a1.x;
            As[kk + 1][r1] = a1.y; As[kk + 1][r1 + 1] = a1.y;
            As[kk + 2][r1] = a1.z; As[kk + 2][r1 + 1] = a1.z;
            As[kk + 3][r1] = a1.w; As[kk + 3][r1 + 1] = a1.w;
            Bks[kk + 0][rowL] = bk.x;
            Bks[kk + 1][rowL] = bk.y;
            Bks[kk + 2][rowL] = bk.z;
            Bks[kk + 3][rowL] = bk.w;
            Bgs[kk + 0][rowL] = bg.x;
            Bgs[kk + 1][rowL] = bg.y;
            Bgs[kk + 2][rowL] = bg.z;
            Bgs[kk + 3][rowL] = bg.w;
        }
        __syncthreads();

#pragma unroll
        for (int k = 0; k < 16; k++) {
            const ulonglong2* ap = (const ulonglong2*)&As[k][16 * ty];
            ulonglong2 p0 = ap[0];
            ulonglong2 p1 = ap[1];
            ulonglong2 p2 = ap[2];
            ulonglong2 p3 = ap[3];
            ulonglong2 bkp = *(const ulonglong2*)&Bks[k][tx * 4];
            ulonglong2 bgp = *(const ulonglong2*)&Bgs[k][tx * 4];
            unsigned long long av[8] = {p0.x, p0.y, p1.x, p1.y, p2.x, p2.y, p3.x, p3.y};
#pragma unroll
            for (int i = 0; i < 8; i++) {
                acc_kv[i][0] = fma2(av[i], bkp.x, acc_kv[i][0]);
                acc_kv[i][1] = fma2(av[i], bkp.y, acc_kv[i][1]);
                acc_g[i][0]  = fma2(av[i], bgp.x, acc_g[i][0]);
                acc_g[i][1]  = fma2(av[i], bgp.y, acc_g[i][1]);
            }
        }
    }

    // Epilogue: gated kv -> scratch
#pragma unroll
    for (int i = 0; i < 8; i++) {
        float2 k01 = unpack2(acc_kv[i][0]);
        float2 k23 = unpack2(acc_kv[i][1]);
        float2 g01 = unpack2(acc_g[i][0]);
        float2 g23 = unpack2(acc_g[i][1]);
        float4 o;
        o.x = k01.x / (1.f + expf(-g01.x));
        o.y = k01.y / (1.f + expf(-g01.y));
        o.z = k23.x / (1.f + expf(-g23.x));
        o.w = k23.y / (1.f + expf(-g23.y));
        size_t row = (size_t)(m0 + ty * 8 + i);
        *(float4*)&g_kvg[row * N_KV + n0 + tx * 4] = o;
    }
}

// ---------------------------------------------------------------------------
// Kernel 3: chunk combine + RMSNorm + partial RoPE.
//   One block per (c, b); 512 threads = one per output dim d.
// ---------------------------------------------------------------------------
__global__ void __launch_bounds__(512) combine_kernel(const float* __restrict__ cosb,
                                                      const float* __restrict__ sinb,
                                                      const float* __restrict__ nw,
                                                      float* __restrict__ out) {
    __shared__ float sh[512];
    __shared__ float wsum[16];
    __shared__ float s_rstd;

    const int d = threadIdx.x;
    const int c = blockIdx.x;
    const int b = blockIdx.y;

    const size_t base = ((size_t)b * S_DIM + (size_t)c * RATIO) * (size_t)N_KV;

    float tacc = 0.f;
    if (c == 0) {
#pragma unroll
        for (int r = 0; r < 4; r++)
            tacc += g_kvg[base + (size_t)r * N_KV + d] * g_w0[r * HD + d];
    } else {
#pragma unroll
        for (int r = 0; r < 4; r++)
            tacc += g_kvg[base + (size_t)r * N_KV + d] * g_w8[r * HD + d];
        const size_t basep = base - (size_t)RATIO * N_KV;
#pragma unroll
        for (int r = 0; r < 4; r++)
            tacc += g_kvg[basep + (size_t)r * N_KV + HD + d] * g_w8[(4 + r) * HD + d];
    }
    sh[d] = tacc;

    // block reduction of sum(t^2)
    float v = tacc * tacc;
#pragma unroll
    for (int off = 16; off; off >>= 1) v += __shfl_xor_sync(0xffffffffu, v, off);
    if ((d & 31) == 0) wsum[d >> 5] = v;
    __syncthreads();
    if (d == 0) {
        float s = 0.f;
#pragma unroll
        for (int w = 0; w < 16; w++) s += wsum[w];
        s_rstd = rsqrtf(s * (1.f / (float)HD) + 1e-6f);
    }
    __syncthreads();
    const float rstd = s_rstd;

    float o;
    if (d < HD - ROPE_D) {
        o = sh[d] * rstd * nw[d];
    } else {
        const int p  = (d - (HD - ROPE_D)) >> 1;
        const int de = (HD - ROPE_D) + 2 * p;
        const int dq = de + 1;
        const float e  = sh[de] * rstd * nw[de];
        const float oo = sh[dq] * rstd * nw[dq];
        const size_t ci = ((size_t)b * C_DIM + c) * (ROPE_D / 2) + p;
        const float cv = cosb[ci];
        const float sv = sinb[ci];
        o = ((d & 1) == 0) ? (e * cv - oo * sv) : (e * sv + oo * cv);
    }
    out[((size_t)b * C_DIM + c) * HD + d] = o;
}

// ---------------------------------------------------------------------------
// Launch. Inputs (metadata order): x, cos, sin, W_kv, W_gate, ape, norm_w.
// Output: (4, 1024, 512) float32.
// ---------------------------------------------------------------------------
extern "C" void kernel_launch(void* const* d_in, const int* in_sizes, int n_in,
                              void* d_out, int out_size) {
    const float* x    = (const float*)d_in[0];
    const float* cosb = (const float*)d_in[1];
    const float* sinb = (const float*)d_in[2];
    const float* Wkv  = (const float*)d_in[3];
    const float* Wg   = (const float*)d_in[4];
    const float* ape  = (const float*)d_in[5];
    const float* nw   = (const float*)d_in[6];
    float* out = (float*)d_out;

    weights_kernel<<<1, 512>>>(ape);
    gemm_kernel<<<dim3(N_KV / 64, M_TOT / 128), 256>>>(x, Wkv, Wg);
    combine_kernel<<<dim3(C_DIM, B_DIM), 512>>>(cosb, sinb, nw, out);
}

// round 3
// speedup vs baseline: 3.4878x; 3.4878x over previous
#include <cuda_runtime.h>
#include <cuda_bf16.h>
#include <cstdint>

// ---------------------------------------------------------------------------
// Problem constants
// ---------------------------------------------------------------------------
#define B_DIM   4
#define S_DIM   4096
#define H_DIM   4096
#define HD      512
#define ROPE_D  64
#define RATIO   4
#define C_DIM   (S_DIM / RATIO)          // 1024
#define M_TOT   (B_DIM * S_DIM)          // 16384
#define K_TOT   H_DIM                    // 4096
#define N_KV    (2 * HD)                 // 1024

// ---------------------------------------------------------------------------
// Device scratch
// ---------------------------------------------------------------------------
__device__ __align__(16) float           g_kvg[(size_t)M_TOT * N_KV];   // 64 MiB
__device__ __align__(16) float           g_w8[8 * HD];
__device__ __align__(16) float           g_w0[4 * HD];
__device__ __align__(1024) __nv_bfloat16 g_Xhi[(size_t)M_TOT * K_TOT];  // 128 MiB
__device__ __align__(1024) __nv_bfloat16 g_Xlo[(size_t)M_TOT * K_TOT];  // 128 MiB
__device__ __align__(1024) __nv_bfloat16 g_Whi[(size_t)2048 * K_TOT];   // rows 0-1023 kv, 1024-2047 gate
__device__ __align__(1024) __nv_bfloat16 g_Wlo[(size_t)2048 * K_TOT];

// ---------------------------------------------------------------------------
// PTX helpers (all plain sm_80+ features — no 'a'-suffix instructions)
// ---------------------------------------------------------------------------
__device__ __forceinline__ uint32_t smem_u32(const void* p) {
    uint32_t a;
    asm("{ .reg .u64 t; cvta.to.shared.u64 t, %1; cvt.u32.u64 %0, t; }"
        : "=r"(a) : "l"(p));
    return a;
}

#define CP16(s, g) \
    asm volatile("cp.async.cg.shared.global [%0], [%1], 16;" :: "r"(s), "l"(g))
#define CP_COMMIT()  asm volatile("cp.async.commit_group;" ::: "memory")
#define CP_WAIT2()   asm volatile("cp.async.wait_group 2;" ::: "memory")
#define CP_WAIT0()   asm volatile("cp.async.wait_group 0;" ::: "memory")

#define LDSM4(r, addr) \
    asm volatile("ldmatrix.sync.aligned.m8n8.x4.shared.b16 {%0,%1,%2,%3}, [%4];" \
                 : "=r"((r)[0]), "=r"((r)[1]), "=r"((r)[2]), "=r"((r)[3]) : "r"(addr))

#define MMA16816(d, a, b0, b1) \
    asm volatile("mma.sync.aligned.m16n8k16.row.col.f32.bf16.bf16.f32 " \
                 "{%0,%1,%2,%3}, {%4,%5,%6,%7}, {%8,%9}, {%0,%1,%2,%3};" \
                 : "+f"((d)[0]), "+f"((d)[1]), "+f"((d)[2]), "+f"((d)[3]) \
                 : "r"((a)[0]), "r"((a)[1]), "r"((a)[2]), "r"((a)[3]), \
                   "r"(b0), "r"(b1))

// ---------------------------------------------------------------------------
// Kernel: ape -> softmax weight tables
// ---------------------------------------------------------------------------
__global__ void weights_kernel(const float* __restrict__ ape) {
    int d = threadIdx.x;  // 0..511
    float v[8];
#pragma unroll
    for (int r = 0; r < 4; r++) {
        v[r]     = ape[r * 1024 + d];
        v[4 + r] = ape[r * 1024 + 512 + d];
    }
    float m4 = v[0];
#pragma unroll
    for (int i = 1; i < 4; i++) m4 = fmaxf(m4, v[i]);
    float e4[4]; float s4 = 0.f;
#pragma unroll
    for (int i = 0; i < 4; i++) { e4[i] = expf(v[i] - m4); s4 += e4[i]; }
    float inv4 = 1.f / s4;
#pragma unroll
    for (int i = 0; i < 4; i++) g_w0[i * HD + d] = e4[i] * inv4;
    float m8 = v[0];
#pragma unroll
    for (int i = 1; i < 8; i++) m8 = fmaxf(m8, v[i]);
    float e8[8]; float s8 = 0.f;
#pragma unroll
    for (int i = 0; i < 8; i++) { e8[i] = expf(v[i] - m8); s8 += e8[i]; }
    float inv8 = 1.f / s8;
#pragma unroll
    for (int i = 0; i < 8; i++) g_w8[i * HD + d] = e8[i] * inv8;
}

// ---------------------------------------------------------------------------
// Conversion: fp32 -> (bf16 hi, bf16 lo)
// ---------------------------------------------------------------------------
__device__ __forceinline__ unsigned pk_bf2(float a, float b, float& ra, float& rb) {
    __nv_bfloat16 ha = __float2bfloat16_rn(a);
    __nv_bfloat16 hb = __float2bfloat16_rn(b);
    ra = a - __bfloat162float(ha);
    rb = b - __bfloat162float(hb);
    __nv_bfloat162 t(ha, hb);
    return *reinterpret_cast<unsigned*>(&t);
}
__device__ __forceinline__ unsigned pk_lo(float a, float b) {
    __nv_bfloat162 t(__float2bfloat16_rn(a), __float2bfloat16_rn(b));
    return *reinterpret_cast<unsigned*>(&t);
}

__global__ void __launch_bounds__(256) convX_kernel(const float4* __restrict__ x) {
    size_t i = (size_t)blockIdx.x * 256 + threadIdx.x;   // 16,777,216 float4
    float4 v = x[i];
    float rx, ry, rz, rw;
    uint2 H, L;
    H.x = pk_bf2(v.x, v.y, rx, ry);
    H.y = pk_bf2(v.z, v.w, rz, rw);
    L.x = pk_lo(rx, ry);
    L.y = pk_lo(rz, rw);
    reinterpret_cast<uint2*>(g_Xhi)[i] = H;
    reinterpret_cast<uint2*>(g_Xlo)[i] = L;
}

__global__ void __launch_bounds__(256) convW_kernel(const float* __restrict__ wkv,
                                                    const float* __restrict__ wg) {
    size_t i = (size_t)blockIdx.x * 256 + threadIdx.x;   // 2,097,152 float4
    size_t e0 = i * 4;
    size_t row = e0 >> 12;
    size_t k = e0 & 4095;
    const float* src = (row < 1024) ? (wkv + row * 4096 + k)
                                    : (wg + (row - 1024) * 4096 + k);
    float4 v = *reinterpret_cast<const float4*>(src);
    float rx, ry, rz, rw;
    uint2 H, L;
    H.x = pk_bf2(v.x, v.y, rx, ry);
    H.y = pk_bf2(v.z, v.w, rz, rw);
    L.x = pk_lo(rx, ry);
    L.y = pk_lo(rz, rw);
    reinterpret_cast<uint2*>(g_Whi)[i] = H;
    reinterpret_cast<uint2*>(g_Wlo)[i] = L;
}

// ---------------------------------------------------------------------------
// HMMA GEMM: per CTA 128 M x (64 kv + 64 gate), K=4096 in 128 chunks of 32,
// 3 bf16 passes, 4-stage cp.async pipeline, gated result -> g_kvg.
//
// SMEM stage layout (32 KB): Ahi[128x32] Alo[128x32] Bhi[128x32] Blo[128x32]
//   (B rows 0-63 = kv rows n0.., rows 64-127 = gate rows 1024+n0..)
// Row layout: 64 B per row in 4 chunks of 16 B, phys chunk = c ^ ((row>>1)&3)
// ---------------------------------------------------------------------------
#define NST      4
#define STG      32768
#define SMEM_SZ  (NST * STG)   // 131072
#define CHUNKS   128

__global__ void __launch_bounds__(256, 1) gemm_mma() {
    extern __shared__ char ds[];
    const uint32_t sb = smem_u32(ds);
    const int t = threadIdx.x;
    const int m0 = blockIdx.y * 128;
    const int n0 = blockIdx.x * 64;

    // ---------------- loader setup ----------------
    const int lr = t >> 2;      // 0..63
    const int lc = t & 3;
    const __nv_bfloat16* pAh = g_Xhi + (size_t)(m0 + lr) * 4096 + lc * 8;
    const __nv_bfloat16* pAl = g_Xlo + (size_t)(m0 + lr) * 4096 + lc * 8;
    const __nv_bfloat16* pBhk = g_Whi + (size_t)(n0 + lr) * 4096 + lc * 8;
    const __nv_bfloat16* pBhg = g_Whi + (size_t)(1024 + n0 + lr) * 4096 + lc * 8;
    const __nv_bfloat16* pBlk = g_Wlo + (size_t)(n0 + lr) * 4096 + lc * 8;
    const __nv_bfloat16* pBlg = g_Wlo + (size_t)(1024 + n0 + lr) * 4096 + lc * 8;
    const uint32_t da = lr * 64 + ((lc ^ ((lr >> 1) & 3)) << 4);  // row lr; row lr+64 at +4096
    const size_t AROW64 = (size_t)64 * 4096;

    // ---------------- compute setup ----------------
    const int lane = t & 31;
    const int wid = t >> 5;
    const int wm = wid & 1;        // m half (64 rows)
    const int wn = wid >> 1;       // n quarter (32 cols); 0,1 = kv; 2,3 = gate
    const int arow = (lane & 7) | (((lane >> 3) & 1) << 3);
    const int akh = (lane >> 4) & 1;
    const int brow = (lane & 7) | (((lane >> 4) & 1) << 3);
    const int bkh = (lane >> 3) & 1;
    const int rowAb = wm * 64 + arow;
    const int rowBb = wn * 32 + brow;
    const int sA = (rowAb >> 1) & 3;
    const int sB = (rowBb >> 1) & 3;

    float acc[4][4][4];
#pragma unroll
    for (int i = 0; i < 4; i++)
#pragma unroll
        for (int j = 0; j < 4; j++)
#pragma unroll
            for (int q = 0; q < 4; q++) acc[i][j][q] = 0.f;

    // ---------------- prologue: fill 3 stages ----------------
#pragma unroll
    for (int s = 0; s < 3; s++) {
        const uint32_t st = sb + s * STG;
        const size_t k = (size_t)s * 32;
        CP16(st + da,               pAh + k);
        CP16(st + da + 4096,        pAh + k + AROW64);
        CP16(st + 8192 + da,        pAl + k);
        CP16(st + 8192 + da + 4096, pAl + k + AROW64);
        CP16(st + 16384 + da,        pBhk + k);
        CP16(st + 16384 + da + 4096, pBhg + k);
        CP16(st + 24576 + da,        pBlk + k);
        CP16(st + 24576 + da + 4096, pBlg + k);
        CP_COMMIT();
    }

    // ---------------- main pipeline ----------------
    for (int c = 0; c < CHUNKS; c++) {
        CP_WAIT2();
        __syncthreads();

        // issue chunk c+3 into slot (c+3)&3
        if (c + 3 < CHUNKS) {
            const uint32_t st = sb + ((c + 3) & 3) * STG;
            const size_t k = (size_t)(c + 3) * 32;
            CP16(st + da,               pAh + k);
            CP16(st + da + 4096,        pAh + k + AROW64);
            CP16(st + 8192 + da,        pAl + k);
            CP16(st + 8192 + da + 4096, pAl + k + AROW64);
            CP16(st + 16384 + da,        pBhk + k);
            CP16(st + 16384 + da + 4096, pBhg + k);
            CP16(st + 24576 + da,        pBlk + k);
            CP16(st + 24576 + da + 4096, pBlg + k);
        }
        CP_COMMIT();

        // compute on slot c&3
        const uint32_t st = sb + (c & 3) * STG;
        const uint32_t stAh = st;
        const uint32_t stAl = st + 8192;
        const uint32_t stBh = st + 16384;
        const uint32_t stBl = st + 24576;

#pragma unroll
        for (int ks = 0; ks < 2; ks++) {
            uint32_t ah[4][4], al[4][4], bh[2][4], bl[2][4];
            const uint32_t pcA = (uint32_t)(((ks * 2 + akh) ^ sA) << 4);
            const uint32_t pcB = (uint32_t)(((ks * 2 + bkh) ^ sB) << 4);
#pragma unroll
            for (int mf = 0; mf < 4; mf++) {
                const uint32_t ro = (uint32_t)(rowAb + mf * 16) * 64 + pcA;
                LDSM4(ah[mf], stAh + ro);
                LDSM4(al[mf], stAl + ro);
            }
#pragma unroll
            for (int q = 0; q < 2; q++) {
                const uint32_t ro = (uint32_t)(rowBb + q * 16) * 64 + pcB;
                LDSM4(bh[q], stBh + ro);
                LDSM4(bl[q], stBl + ro);
            }
#pragma unroll
            for (int mf = 0; mf < 4; mf++) {
#pragma unroll
                for (int nf = 0; nf < 4; nf++) {
                    const int q = nf >> 1;
                    const int h = (nf & 1) * 2;
                    MMA16816(acc[mf][nf], ah[mf], bh[q][h], bh[q][h + 1]);
                    MMA16816(acc[mf][nf], ah[mf], bl[q][h], bl[q][h + 1]);
                    MMA16816(acc[mf][nf], al[mf], bh[q][h], bh[q][h + 1]);
                }
            }
        }
    }

    CP_WAIT0();
    __syncthreads();

    // ---------------- epilogue: gate exchange + store ----------------
    float* sg = reinterpret_cast<float*>(ds);   // [128][66] sigmoid(gate)
    const int g  = lane >> 2;
    const int tg = lane & 3;

    if (wn >= 2) {
        const int cb = (wn - 2) * 32;
#pragma unroll
        for (int mf = 0; mf < 4; mf++) {
#pragma unroll
            for (int nf = 0; nf < 4; nf++) {
                const int row0 = wm * 64 + mf * 16 + g;
                const int col = cb + nf * 8 + tg * 2;
                sg[row0 * 66 + col]           = 1.f / (1.f + expf(-acc[mf][nf][0]));
                sg[row0 * 66 + col + 1]       = 1.f / (1.f + expf(-acc[mf][nf][1]));
                sg[(row0 + 8) * 66 + col]     = 1.f / (1.f + expf(-acc[mf][nf][2]));
                sg[(row0 + 8) * 66 + col + 1] = 1.f / (1.f + expf(-acc[mf][nf][3]));
            }
        }
    }
    __syncthreads();
    if (wn < 2) {
        const int cb = wn * 32;
#pragma unroll
        for (int mf = 0; mf < 4; mf++) {
#pragma unroll
            for (int nf = 0; nf < 4; nf++) {
                const int row0 = wm * 64 + mf * 16 + g;
                const int colw = cb + nf * 8 + tg * 2;
                float2 v0, v1;
                v0.x = acc[mf][nf][0] * sg[row0 * 66 + colw];
                v0.y = acc[mf][nf][1] * sg[row0 * 66 + colw + 1];
                v1.x = acc[mf][nf][2] * sg[(row0 + 8) * 66 + colw];
                v1.y = acc[mf][nf][3] * sg[(row0 + 8) * 66 + colw + 1];
                *reinterpret_cast<float2*>(&g_kvg[(size_t)(m0 + row0) * N_KV + n0 + colw]) = v0;
                *reinterpret_cast<float2*>(&g_kvg[(size_t)(m0 + row0 + 8) * N_KV + n0 + colw]) = v1;
            }
        }
    }
}

// ---------------------------------------------------------------------------
// Combine + RMSNorm + partial RoPE (validated R1)
// ---------------------------------------------------------------------------
__global__ void __launch_bounds__(512) combine_kernel(const float* __restrict__ cosb,
                                                      const float* __restrict__ sinb,
                                                      const float* __restrict__ nw,
                                                      float* __restrict__ out) {
    __shared__ float sh[512];
    __shared__ float wsum[16];
    __shared__ float s_rstd;

    const int d = threadIdx.x;
    const int c = blockIdx.x;
    const int b = blockIdx.y;

    const size_t base = ((size_t)b * S_DIM + (size_t)c * RATIO) * (size_t)N_KV;

    float tacc = 0.f;
    if (c == 0) {
#pragma unroll
        for (int r = 0; r < 4; r++)
            tacc += g_kvg[base + (size_t)r * N_KV + d] * g_w0[r * HD + d];
    } else {
#pragma unroll
        for (int r = 0; r < 4; r++)
            tacc += g_kvg[base + (size_t)r * N_KV + d] * g_w8[r * HD + d];
        const size_t basep = base - (size_t)RATIO * N_KV;
#pragma unroll
        for (int r = 0; r < 4; r++)
            tacc += g_kvg[basep + (size_t)r * N_KV + HD + d] * g_w8[(4 + r) * HD + d];
    }
    sh[d] = tacc;

    float v = tacc * tacc;
#pragma unroll
    for (int off = 16; off; off >>= 1) v += __shfl_xor_sync(0xffffffffu, v, off);
    if ((d & 31) == 0) wsum[d >> 5] = v;
    __syncthreads();
    if (d == 0) {
        float s = 0.f;
#pragma unroll
        for (int w = 0; w < 16; w++) s += wsum[w];
        s_rstd = rsqrtf(s * (1.f / (float)HD) + 1e-6f);
    }
    __syncthreads();
    const float rstd = s_rstd;

    float o;
    if (d < HD - ROPE_D) {
        o = sh[d] * rstd * nw[d];
    } else {
        const int p  = (d - (HD - ROPE_D)) >> 1;
        const int de = (HD - ROPE_D) + 2 * p;
        const int dq = de + 1;
        const float e  = sh[de] * rstd * nw[de];
        const float oo = sh[dq] * rstd * nw[dq];
        const size_t ci = ((size_t)b * C_DIM + c) * (ROPE_D / 2) + p;
        const float cv = cosb[ci];
        const float sv = sinb[ci];
        o = ((d & 1) == 0) ? (e * cv - oo * sv) : (e * sv + oo * cv);
    }
    out[((size_t)b * C_DIM + c) * HD + d] = o;
}

// ---------------------------------------------------------------------------
// Launch
// ---------------------------------------------------------------------------
extern "C" void kernel_launch(void* const* d_in, const int* in_sizes, int n_in,
                              void* d_out, int out_size) {
    const float* x    = (const float*)d_in[0];
    const float* cosb = (const float*)d_in[1];
    const float* sinb = (const float*)d_in[2];
    const float* Wkv  = (const float*)d_in[3];
    const float* Wg   = (const float*)d_in[4];
    const float* ape  = (const float*)d_in[5];
    const float* nw   = (const float*)d_in[6];
    float* out = (float*)d_out;

    cudaFuncSetAttribute(gemm_mma, cudaFuncAttributeMaxDynamicSharedMemorySize, SMEM_SZ);

    weights_kernel<<<1, 512>>>(ape);
    convX_kernel<<<65536, 256>>>((const float4*)x);
    convW_kernel<<<8192, 256>>>(Wkv, Wg);
    gemm_mma<<<dim3(16, 128), 256, SMEM_SZ>>>();
    combine_kernel<<<dim3(C_DIM, B_DIM), 512>>>(cosb, sinb, nw, out);
}

// round 4
// speedup vs baseline: 4.1591x; 1.1925x over previous
#include <cuda_runtime.h>
#include <cuda_bf16.h>
#include <cstdint>

// ---------------------------------------------------------------------------
// Problem constants
// ---------------------------------------------------------------------------
#define B_DIM   4
#define S_DIM   4096
#define H_DIM   4096
#define HD      512
#define ROPE_D  64
#define RATIO   4
#define C_DIM   (S_DIM / RATIO)          // 1024
#define M_TOT   (B_DIM * S_DIM)          // 16384
#define K_TOT   H_DIM                    // 4096
#define N_KV    (2 * HD)                 // 1024

// ---------------------------------------------------------------------------
// Device scratch
// ---------------------------------------------------------------------------
__device__ __align__(16) float           g_kvg[(size_t)M_TOT * N_KV];   // 64 MiB
__device__ __align__(16) float           g_w8[8 * HD];
__device__ __align__(16) float           g_w0[4 * HD];
__device__ __align__(1024) __nv_bfloat16 g_Xhi[(size_t)M_TOT * K_TOT];  // 128 MiB
__device__ __align__(1024) __nv_bfloat16 g_Xlo[(size_t)M_TOT * K_TOT];  // 128 MiB
__device__ __align__(1024) __nv_bfloat16 g_Whi[(size_t)2048 * K_TOT];   // rows 0-1023 kv, 1024-2047 gate
__device__ __align__(1024) __nv_bfloat16 g_Wlo[(size_t)2048 * K_TOT];

// ---------------------------------------------------------------------------
// PTX helpers (plain sm_80+ features only)
// ---------------------------------------------------------------------------
__device__ __forceinline__ uint32_t smem_u32(const void* p) {
    uint32_t a;
    asm("{ .reg .u64 t; cvta.to.shared.u64 t, %1; cvt.u32.u64 %0, t; }"
        : "=r"(a) : "l"(p));
    return a;
}

#define CP16(s, g) \
    asm volatile("cp.async.cg.shared.global [%0], [%1], 16;" :: "r"(s), "l"(g))
#define CP_COMMIT()  asm volatile("cp.async.commit_group;" ::: "memory")
#define CP_WAIT1()   asm volatile("cp.async.wait_group 1;" ::: "memory")
#define CP_WAIT0()   asm volatile("cp.async.wait_group 0;" ::: "memory")

#define LDSM4(r, addr) \
    asm volatile("ldmatrix.sync.aligned.m8n8.x4.shared.b16 {%0,%1,%2,%3}, [%4];" \
                 : "=r"((r)[0]), "=r"((r)[1]), "=r"((r)[2]), "=r"((r)[3]) : "r"(addr))

#define MMA16816(d, a, b0, b1) \
    asm volatile("mma.sync.aligned.m16n8k16.row.col.f32.bf16.bf16.f32 " \
                 "{%0,%1,%2,%3}, {%4,%5,%6,%7}, {%8,%9}, {%0,%1,%2,%3};" \
                 : "+f"((d)[0]), "+f"((d)[1]), "+f"((d)[2]), "+f"((d)[3]) \
                 : "r"((a)[0]), "r"((a)[1]), "r"((a)[2]), "r"((a)[3]), \
                   "r"(b0), "r"(b1))

// ---------------------------------------------------------------------------
// Kernel: ape -> softmax weight tables
// ---------------------------------------------------------------------------
__global__ void weights_kernel(const float* __restrict__ ape) {
    int d = threadIdx.x;  // 0..511
    float v[8];
#pragma unroll
    for (int r = 0; r < 4; r++) {
        v[r]     = ape[r * 1024 + d];
        v[4 + r] = ape[r * 1024 + 512 + d];
    }
    float m4 = v[0];
#pragma unroll
    for (int i = 1; i < 4; i++) m4 = fmaxf(m4, v[i]);
    float e4[4]; float s4 = 0.f;
#pragma unroll
    for (int i = 0; i < 4; i++) { e4[i] = expf(v[i] - m4); s4 += e4[i]; }
    float inv4 = 1.f / s4;
#pragma unroll
    for (int i = 0; i < 4; i++) g_w0[i * HD + d] = e4[i] * inv4;
    float m8 = v[0];
#pragma unroll
    for (int i = 1; i < 8; i++) m8 = fmaxf(m8, v[i]);
    float e8[8]; float s8 = 0.f;
#pragma unroll
    for (int i = 0; i < 8; i++) { e8[i] = expf(v[i] - m8); s8 += e8[i]; }
    float inv8 = 1.f / s8;
#pragma unroll
    for (int i = 0; i < 8; i++) g_w8[i * HD + d] = e8[i] * inv8;
}

// ---------------------------------------------------------------------------
// Conversion: fp32 -> (bf16 hi, bf16 lo)
// ---------------------------------------------------------------------------
__device__ __forceinline__ unsigned pk_bf2(float a, float b, float& ra, float& rb) {
    __nv_bfloat16 ha = __float2bfloat16_rn(a);
    __nv_bfloat16 hb = __float2bfloat16_rn(b);
    ra = a - __bfloat162float(ha);
    rb = b - __bfloat162float(hb);
    __nv_bfloat162 t(ha, hb);
    return *reinterpret_cast<unsigned*>(&t);
}
__device__ __forceinline__ unsigned pk_lo(float a, float b) {
    __nv_bfloat162 t(__float2bfloat16_rn(a), __float2bfloat16_rn(b));
    return *reinterpret_cast<unsigned*>(&t);
}

__global__ void __launch_bounds__(256) convX_kernel(const float4* __restrict__ x) {
    size_t i = (size_t)blockIdx.x * 256 + threadIdx.x;   // 16,777,216 float4
    float4 v = x[i];
    float rx, ry, rz, rw;
    uint2 H, L;
    H.x = pk_bf2(v.x, v.y, rx, ry);
    H.y = pk_bf2(v.z, v.w, rz, rw);
    L.x = pk_lo(rx, ry);
    L.y = pk_lo(rz, rw);
    reinterpret_cast<uint2*>(g_Xhi)[i] = H;
    reinterpret_cast<uint2*>(g_Xlo)[i] = L;
}

__global__ void __launch_bounds__(256) convW_kernel(const float* __restrict__ wkv,
                                                    const float* __restrict__ wg) {
    size_t i = (size_t)blockIdx.x * 256 + threadIdx.x;   // 2,097,152 float4
    size_t e0 = i * 4;
    size_t row = e0 >> 12;
    size_t k = e0 & 4095;
    const float* src = (row < 1024) ? (wkv + row * 4096 + k)
                                    : (wg + (row - 1024) * 4096 + k);
    float4 v = *reinterpret_cast<const float4*>(src);
    float rx, ry, rz, rw;
    uint2 H, L;
    H.x = pk_bf2(v.x, v.y, rx, ry);
    H.y = pk_bf2(v.z, v.w, rz, rw);
    L.x = pk_lo(rx, ry);
    L.y = pk_lo(rz, rw);
    reinterpret_cast<uint2*>(g_Whi)[i] = H;
    reinterpret_cast<uint2*>(g_Wlo)[i] = L;
}

// ---------------------------------------------------------------------------
// HMMA GEMM: per CTA 128 M x (64 kv + 64 gate), K=4096 in 128 chunks of 32,
// 3 bf16 passes, 3-stage cp.async pipeline, 2 CTAs/SM, gated -> g_kvg.
//
// SMEM stage (32 KB): Ahi[128x32] Alo[128x32] Bhi[128x32] Blo[128x32]
//   (B rows 0-63 = kv rows n0.., rows 64-127 = gate rows 1024+n0..)
// Row layout: 64 B per row in 4 chunks of 16 B, phys chunk = c ^ ((row>>1)&3)
// ---------------------------------------------------------------------------
#define NST      3
#define STG      32768
#define SMEM_SZ  (NST * STG)   // 98304
#define CHUNKS   128

__global__ void __launch_bounds__(256, 2) gemm_mma() {
    extern __shared__ char ds[];
    const uint32_t sb = smem_u32(ds);
    const int t = threadIdx.x;
    const int m0 = blockIdx.y * 128;
    const int n0 = blockIdx.x * 64;

    // ---------------- loader setup ----------------
    const int lr = t >> 2;      // 0..63
    const int lc = t & 3;
    const __nv_bfloat16* pAh  = g_Xhi + (size_t)(m0 + lr) * 4096 + lc * 8;
    const __nv_bfloat16* pAl  = g_Xlo + (size_t)(m0 + lr) * 4096 + lc * 8;
    const __nv_bfloat16* pBhk = g_Whi + (size_t)(n0 + lr) * 4096 + lc * 8;
    const __nv_bfloat16* pBhg = g_Whi + (size_t)(1024 + n0 + lr) * 4096 + lc * 8;
    const __nv_bfloat16* pBlk = g_Wlo + (size_t)(n0 + lr) * 4096 + lc * 8;
    const __nv_bfloat16* pBlg = g_Wlo + (size_t)(1024 + n0 + lr) * 4096 + lc * 8;
    const uint32_t da = lr * 64 + ((lc ^ ((lr >> 1) & 3)) << 4);
    const size_t AROW64 = (size_t)64 * 4096;

    // ---------------- compute setup ----------------
    const int lane = t & 31;
    const int wid = t >> 5;
    const int wm = wid & 1;        // m half (64 rows)
    const int wn = wid >> 1;       // n quarter (32 cols); 0,1 = kv; 2,3 = gate
    const int arow = (lane & 7) | (((lane >> 3) & 1) << 3);
    const int akh = (lane >> 4) & 1;
    const int brow = (lane & 7) | (((lane >> 4) & 1) << 3);
    const int bkh = (lane >> 3) & 1;
    const int rowAb = wm * 64 + arow;
    const int rowBb = wn * 32 + brow;
    const int sA = (rowAb >> 1) & 3;
    const int sB = (rowBb >> 1) & 3;

    float acc[4][4][4];
#pragma unroll
    for (int i = 0; i < 4; i++)
#pragma unroll
        for (int j = 0; j < 4; j++)
#pragma unroll
            for (int q = 0; q < 4; q++) acc[i][j][q] = 0.f;

    // ---------------- prologue: fill 2 stages ----------------
#pragma unroll
    for (int s = 0; s < 2; s++) {
        const uint32_t st = sb + s * STG;
        const size_t k = (size_t)s * 32;
        CP16(st + da,               pAh + k);
        CP16(st + da + 4096,        pAh + k + AROW64);
        CP16(st + 8192 + da,        pAl + k);
        CP16(st + 8192 + da + 4096, pAl + k + AROW64);
        CP16(st + 16384 + da,        pBhk + k);
        CP16(st + 16384 + da + 4096, pBhg + k);
        CP16(st + 24576 + da,        pBlk + k);
        CP16(st + 24576 + da + 4096, pBlg + k);
        CP_COMMIT();
    }

    // stage slot of chunk c: rotates over 3 slots
    int slot = 0;       // slot of chunk c
    int wslot = 2;      // slot where chunk c+2 goes

    // ---------------- main pipeline ----------------
    for (int c = 0; c < CHUNKS; c++) {
        CP_WAIT1();
        __syncthreads();

        // issue chunk c+2 into wslot
        if (c + 2 < CHUNKS) {
            const uint32_t st = sb + wslot * STG;
            const size_t k = (size_t)(c + 2) * 32;
            CP16(st + da,               pAh + k);
            CP16(st + da + 4096,        pAh + k + AROW64);
            CP16(st + 8192 + da,        pAl + k);
            CP16(st + 8192 + da + 4096, pAl + k + AROW64);
            CP16(st + 16384 + da,        pBhk + k);
            CP16(st + 16384 + da + 4096, pBhg + k);
            CP16(st + 24576 + da,        pBlk + k);
            CP16(st + 24576 + da + 4096, pBlg + k);
        }
        CP_COMMIT();

        // compute on slot
        const uint32_t st = sb + slot * STG;
        const uint32_t stAh = st;
        const uint32_t stAl = st + 8192;
        const uint32_t stBh = st + 16384;
        const uint32_t stBl = st + 24576;

#pragma unroll
        for (int ks = 0; ks < 2; ks++) {
            uint32_t bh[2][4], bl[2][4];
            const uint32_t pcA = (uint32_t)(((ks * 2 + akh) ^ sA) << 4);
            const uint32_t pcB = (uint32_t)(((ks * 2 + bkh) ^ sB) << 4);
#pragma unroll
            for (int q = 0; q < 2; q++) {
                const uint32_t ro = (uint32_t)(rowBb + q * 16) * 64 + pcB;
                LDSM4(bh[q], stBh + ro);
                LDSM4(bl[q], stBl + ro);
            }
#pragma unroll
            for (int mf = 0; mf < 4; mf++) {
                uint32_t ah[4], al[4];
                const uint32_t ro = (uint32_t)(rowAb + mf * 16) * 64 + pcA;
                LDSM4(ah, stAh + ro);
                LDSM4(al, stAl + ro);
#pragma unroll
                for (int nf = 0; nf < 4; nf++) {
                    const int q = nf >> 1;
                    const int h = (nf & 1) * 2;
                    MMA16816(acc[mf][nf], ah, bh[q][h], bh[q][h + 1]);
                    MMA16816(acc[mf][nf], ah, bl[q][h], bl[q][h + 1]);
                    MMA16816(acc[mf][nf], al, bh[q][h], bh[q][h + 1]);
                }
            }
        }

        slot = (slot == 2) ? 0 : slot + 1;
        wslot = (wslot == 2) ? 0 : wslot + 1;
    }

    CP_WAIT0();
    __syncthreads();

    // ---------------- epilogue: gate exchange + store ----------------
    float* sg = reinterpret_cast<float*>(ds);   // [128][66] sigmoid(gate)
    const int g  = lane >> 2;
    const int tg = lane & 3;

    if (wn >= 2) {
        const int cb = (wn - 2) * 32;
#pragma unroll
        for (int mf = 0; mf < 4; mf++) {
#pragma unroll
            for (int nf = 0; nf < 4; nf++) {
                const int row0 = wm * 64 + mf * 16 + g;
                const int col = cb + nf * 8 + tg * 2;
                sg[row0 * 66 + col]           = 1.f / (1.f + __expf(-acc[mf][nf][0]));
                sg[row0 * 66 + col + 1]       = 1.f / (1.f + __expf(-acc[mf][nf][1]));
                sg[(row0 + 8) * 66 + col]     = 1.f / (1.f + __expf(-acc[mf][nf][2]));
                sg[(row0 + 8) * 66 + col + 1] = 1.f / (1.f + __expf(-acc[mf][nf][3]));
            }
        }
    }
    __syncthreads();
    if (wn < 2) {
        const int cb = wn * 32;
#pragma unroll
        for (int mf = 0; mf < 4; mf++) {
#pragma unroll
            for (int nf = 0; nf < 4; nf++) {
                const int row0 = wm * 64 + mf * 16 + g;
                const int colw = cb + nf * 8 + tg * 2;
                float2 v0, v1;
                v0.x = acc[mf][nf][0] * sg[row0 * 66 + colw];
                v0.y = acc[mf][nf][1] * sg[row0 * 66 + colw + 1];
                v1.x = acc[mf][nf][2] * sg[(row0 + 8) * 66 + colw];
                v1.y = acc[mf][nf][3] * sg[(row0 + 8) * 66 + colw + 1];
                *reinterpret_cast<float2*>(&g_kvg[(size_t)(m0 + row0) * N_KV + n0 + colw]) = v0;
                *reinterpret_cast<float2*>(&g_kvg[(size_t)(m0 + row0 + 8) * N_KV + n0 + colw]) = v1;
            }
        }
    }
}

// ---------------------------------------------------------------------------
// Combine + RMSNorm + partial RoPE (validated R1)
// ---------------------------------------------------------------------------
__global__ void __launch_bounds__(512) combine_kernel(const float* __restrict__ cosb,
                                                      const float* __restrict__ sinb,
                                                      const float* __restrict__ nw,
                                                      float* __restrict__ out) {
    __shared__ float sh[512];
    __shared__ float wsum[16];
    __shared__ float s_rstd;

    const int d = threadIdx.x;
    const int c = blockIdx.x;
    const int b = blockIdx.y;

    const size_t base = ((size_t)b * S_DIM + (size_t)c * RATIO) * (size_t)N_KV;

    float tacc = 0.f;
    if (c == 0) {
#pragma unroll
        for (int r = 0; r < 4; r++)
            tacc += g_kvg[base + (size_t)r * N_KV + d] * g_w0[r * HD + d];
    } else {
#pragma unroll
        for (int r = 0; r < 4; r++)
            tacc += g_kvg[base + (size_t)r * N_KV + d] * g_w8[r * HD + d];
        const size_t basep = base - (size_t)RATIO * N_KV;
#pragma unroll
        for (int r = 0; r < 4; r++)
            tacc += g_kvg[basep + (size_t)r * N_KV + HD + d] * g_w8[(4 + r) * HD + d];
    }
    sh[d] = tacc;

    float v = tacc * tacc;
#pragma unroll
    for (int off = 16; off; off >>= 1) v += __shfl_xor_sync(0xffffffffu, v, off);
    if ((d & 31) == 0) wsum[d >> 5] = v;
    __syncthreads();
    if (d == 0) {
        float s = 0.f;
#pragma unroll
        for (int w = 0; w < 16; w++) s += wsum[w];
        s_rstd = rsqrtf(s * (1.f / (float)HD) + 1e-6f);
    }
    __syncthreads();
    const float rstd = s_rstd;

    float o;
    if (d < HD - ROPE_D) {
        o = sh[d] * rstd * nw[d];
    } else {
        const int p  = (d - (HD - ROPE_D)) >> 1;
        const int de = (HD - ROPE_D) + 2 * p;
        const int dq = de + 1;
        const float e  = sh[de] * rstd * nw[de];
        const float oo = sh[dq] * rstd * nw[dq];
        const size_t ci = ((size_t)b * C_DIM + c) * (ROPE_D / 2) + p;
        const float cv = cosb[ci];
        const float sv = sinb[ci];
        o = ((d & 1) == 0) ? (e * cv - oo * sv) : (e * sv + oo * cv);
    }
    out[((size_t)b * C_DIM + c) * HD + d] = o;
}

// ---------------------------------------------------------------------------
// Launch
// ---------------------------------------------------------------------------
extern "C" void kernel_launch(void* const* d_in, const int* in_sizes, int n_in,
                              void* d_out, int out_size) {
    const float* x    = (const float*)d_in[0];
    const float* cosb = (const float*)d_in[1];
    const float* sinb = (const float*)d_in[2];
    const float* Wkv  = (const float*)d_in[3];
    const float* Wg   = (const float*)d_in[4];
    const float* ape  = (const float*)d_in[5];
    const float* nw   = (const float*)d_in[6];
    float* out = (float*)d_out;

    cudaFuncSetAttribute(gemm_mma, cudaFuncAttributeMaxDynamicSharedMemorySize, SMEM_SZ);

    weights_kernel<<<1, 512>>>(ape);
    convX_kernel<<<65536, 256>>>((const float4*)x);
    convW_kernel<<<8192, 256>>>(Wkv, Wg);
    gemm_mma<<<dim3(16, 128), 256, SMEM_SZ>>>();
    combine_kernel<<<dim3(C_DIM, B_DIM), 512>>>(cosb, sinb, nw, out);
}

// round 5
// speedup vs baseline: 4.6469x; 1.1173x over previous
#include <cuda.h>
#include <cuda_runtime.h>
#include <cuda_bf16.h>
#include <cstdint>

// ---------------------------------------------------------------------------
// Problem constants
// ---------------------------------------------------------------------------
#define B_DIM   4
#define S_DIM   4096
#define H_DIM   4096
#define HD      512
#define ROPE_D  64
#define RATIO   4
#define C_DIM   (S_DIM / RATIO)          // 1024
#define M_TOT   (B_DIM * S_DIM)          // 16384
#define K_TOT   H_DIM                    // 4096
#define N_KV    (2 * HD)                 // 1024

// ---------------------------------------------------------------------------
// Device scratch
// ---------------------------------------------------------------------------
__device__ __align__(16) float           g_kvg[(size_t)M_TOT * N_KV];   // 64 MiB
__device__ __align__(16) float           g_w8[8 * HD];
__device__ __align__(16) float           g_w0[4 * HD];
__device__ __align__(1024) __nv_bfloat16 g_Xhi[(size_t)M_TOT * K_TOT];  // 128 MiB
__device__ __align__(1024) __nv_bfloat16 g_Xlo[(size_t)M_TOT * K_TOT];  // 128 MiB
__device__ __align__(1024) __nv_bfloat16 g_Whi[(size_t)2048 * K_TOT];   // rows 0-1023 kv, 1024-2047 gate
__device__ __align__(1024) __nv_bfloat16 g_Wlo[(size_t)2048 * K_TOT];

// ---------------------------------------------------------------------------
// PTX helpers (plain sm_90-level features only; no 'a'-suffix instructions)
// ---------------------------------------------------------------------------
__device__ __forceinline__ uint32_t smem_u32(const void* p) {
    uint32_t a;
    asm("{ .reg .u64 t; cvta.to.shared.u64 t, %1; cvt.u32.u64 %0, t; }"
        : "=r"(a) : "l"(p));
    return a;
}

#define CP16(s, g) \
    asm volatile("cp.async.cg.shared.global [%0], [%1], 16;" :: "r"(s), "l"(g))
#define CP_COMMIT()  asm volatile("cp.async.commit_group;" ::: "memory")
#define CP_WAIT1()   asm volatile("cp.async.wait_group 1;" ::: "memory")
#define CP_WAIT0()   asm volatile("cp.async.wait_group 0;" ::: "memory")

#define LDSM4(r, addr) \
    asm volatile("ldmatrix.sync.aligned.m8n8.x4.shared.b16 {%0,%1,%2,%3}, [%4];" \
                 : "=r"((r)[0]), "=r"((r)[1]), "=r"((r)[2]), "=r"((r)[3]) : "r"(addr))

#define MMA16816(d, a, b0, b1) \
    asm volatile("mma.sync.aligned.m16n8k16.row.col.f32.bf16.bf16.f32 " \
                 "{%0,%1,%2,%3}, {%4,%5,%6,%7}, {%8,%9}, {%0,%1,%2,%3};" \
                 : "+f"((d)[0]), "+f"((d)[1]), "+f"((d)[2]), "+f"((d)[3]) \
                 : "r"((a)[0]), "r"((a)[1]), "r"((a)[2]), "r"((a)[3]), \
                   "r"(b0), "r"(b1))

#define MBARRIER_INIT(addr, cnt) \
    asm volatile("mbarrier.init.shared.b64 [%0], %1;" :: "r"((uint32_t)(addr)), "r"((uint32_t)(cnt)) : "memory")
#define MBARRIER_ARRIVE(addr) \
    asm volatile("mbarrier.arrive.shared.b64 _, [%0];" :: "r"((uint32_t)(addr)) : "memory")
#define MBARRIER_EXPECT_TX(addr, bytes) \
    asm volatile("mbarrier.arrive.expect_tx.shared.b64 _, [%0], %1;" :: "r"((uint32_t)(addr)), "r"((uint32_t)(bytes)) : "memory")
#define MBARRIER_WAIT_PARITY(addr, parity) do {                                   \
    uint32_t _mb = (uint32_t)(addr);                                              \
    uint32_t _ph = (uint32_t)(parity);                                            \
    asm volatile(                                                                 \
        "{\n\t.reg .pred P1;\n\t"                                                 \
        "WAIT_LOOP_%=:\n\t"                                                       \
        "mbarrier.try_wait.parity.acquire.cta.shared::cta.b64 P1, [%0], %1, 0x989680;\n\t" \
        "@P1 bra.uni WAIT_DONE_%=;\n\t"                                           \
        "bra.uni WAIT_LOOP_%=;\n\t"                                               \
        "WAIT_DONE_%=:\n\t}"                                                      \
        :: "r"(_mb), "r"(_ph) : "memory");                                        \
} while (0)

#define TMA2D(smem_addr, map_ptr, cx, cy, mbar) \
    asm volatile("cp.async.bulk.tensor.2d.shared::cta.global.tile.mbarrier::complete_tx::bytes " \
                 "[%0], [%1, {%2, %3}], [%4];"                                    \
                 :: "r"((uint32_t)(smem_addr)), "l"(map_ptr),                     \
                    "r"((int32_t)(cx)), "r"((int32_t)(cy)),                       \
                    "r"((uint32_t)(mbar)) : "memory")

// ---------------------------------------------------------------------------
// Kernel: ape -> softmax weight tables
// ---------------------------------------------------------------------------
__global__ void weights_kernel(const float* __restrict__ ape) {
    int d = threadIdx.x;  // 0..511
    float v[8];
#pragma unroll
    for (int r = 0; r < 4; r++) {
        v[r]     = ape[r * 1024 + d];
        v[4 + r] = ape[r * 1024 + 512 + d];
    }
    float m4 = v[0];
#pragma unroll
    for (int i = 1; i < 4; i++) m4 = fmaxf(m4, v[i]);
    float e4[4]; float s4 = 0.f;
#pragma unroll
    for (int i = 0; i < 4; i++) { e4[i] = expf(v[i] - m4); s4 += e4[i]; }
    float inv4 = 1.f / s4;
#pragma unroll
    for (int i = 0; i < 4; i++) g_w0[i * HD + d] = e4[i] * inv4;
    float m8 = v[0];
#pragma unroll
    for (int i = 1; i < 8; i++) m8 = fmaxf(m8, v[i]);
    float e8[8]; float s8 = 0.f;
#pragma unroll
    for (int i = 0; i < 8; i++) { e8[i] = expf(v[i] - m8); s8 += e8[i]; }
    float inv8 = 1.f / s8;
#pragma unroll
    for (int i = 0; i < 8; i++) g_w8[i * HD + d] = e8[i] * inv8;
}

// ---------------------------------------------------------------------------
// Conversion: fp32 -> (bf16 hi, bf16 lo)
// ---------------------------------------------------------------------------
__device__ __forceinline__ unsigned pk_bf2(float a, float b, float& ra, float& rb) {
    __nv_bfloat16 ha = __float2bfloat16_rn(a);
    __nv_bfloat16 hb = __float2bfloat16_rn(b);
    ra = a - __bfloat162float(ha);
    rb = b - __bfloat162float(hb);
    __nv_bfloat162 t(ha, hb);
    return *reinterpret_cast<unsigned*>(&t);
}
__device__ __forceinline__ unsigned pk_lo(float a, float b) {
    __nv_bfloat162 t(__float2bfloat16_rn(a), __float2bfloat16_rn(b));
    return *reinterpret_cast<unsigned*>(&t);
}

__global__ void __launch_bounds__(256) convX_kernel(const float4* __restrict__ x) {
    size_t i = (size_t)blockIdx.x * 256 + threadIdx.x;   // 16,777,216 float4
    float4 v = x[i];
    float rx, ry, rz, rw;
    uint2 H, L;
    H.x = pk_bf2(v.x, v.y, rx, ry);
    H.y = pk_bf2(v.z, v.w, rz, rw);
    L.x = pk_lo(rx, ry);
    L.y = pk_lo(rz, rw);
    reinterpret_cast<uint2*>(g_Xhi)[i] = H;
    reinterpret_cast<uint2*>(g_Xlo)[i] = L;
}

__global__ void __launch_bounds__(256) convW_kernel(const float* __restrict__ wkv,
                                                    const float* __restrict__ wg) {
    size_t i = (size_t)blockIdx.x * 256 + threadIdx.x;   // 2,097,152 float4
    size_t e0 = i * 4;
    size_t row = e0 >> 12;
    size_t k = e0 & 4095;
    const float* src = (row < 1024) ? (wkv + row * 4096 + k)
                                    : (wg + (row - 1024) * 4096 + k);
    float4 v = *reinterpret_cast<const float4*>(src);
    float rx, ry, rz, rw;
    uint2 H, L;
    H.x = pk_bf2(v.x, v.y, rx, ry);
    H.y = pk_bf2(v.z, v.w, rz, rw);
    L.x = pk_lo(rx, ry);
    L.y = pk_lo(rz, rw);
    reinterpret_cast<uint2*>(g_Whi)[i] = H;
    reinterpret_cast<uint2*>(g_Wlo)[i] = L;
}

// ---------------------------------------------------------------------------
// GEMM common geometry:
//   CTA: 128 M x (64 kv + 64 gate), K=4096 in 128 chunks of 32.
//   Stage (32 KB): Ahi[128x32] Alo[128x32] Bhi[128x32] Blo[128x32]
//   Row = 64 B, 4 chunks of 16 B, phys chunk = c ^ ((row>>1)&3)  (== TMA SW64)
// ---------------------------------------------------------------------------
#define NST      3
#define STG      32768
#define CHUNKS   128
#define SMEM_TMA (2048 + NST * STG)   // header (align slack + barriers) + stages
#define SMEM_CPA (NST * STG)

// ---------------------------------------------------------------------------
// TMA + mbarrier GEMM (primary path)
// ---------------------------------------------------------------------------
__device__ __forceinline__ void issue_stage(
    uint32_t st, int c, int m0, int n0, uint32_t fullb,
    const CUtensorMap* mXhi, const CUtensorMap* mXlo,
    const CUtensorMap* mWhi, const CUtensorMap* mWlo)
{
    const int k0 = c * 32;
    MBARRIER_EXPECT_TX(fullb, STG);
    TMA2D(st +     0, mXhi, k0, m0,        fullb);
    TMA2D(st +  8192, mXlo, k0, m0,        fullb);
    TMA2D(st + 16384, mWhi, k0, n0,        fullb);
    TMA2D(st + 20480, mWhi, k0, 1024 + n0, fullb);
    TMA2D(st + 24576, mWlo, k0, n0,        fullb);
    TMA2D(st + 28672, mWlo, k0, 1024 + n0, fullb);
}

__global__ void __launch_bounds__(256, 2) gemm_tma(
    const __grid_constant__ CUtensorMap mXhi,
    const __grid_constant__ CUtensorMap mXlo,
    const __grid_constant__ CUtensorMap mWhi,
    const __grid_constant__ CUtensorMap mWlo)
{
    extern __shared__ char ds[];
    const uint32_t raw  = smem_u32(ds);
    const uint32_t base = (raw + 1023u) & ~1023u;   // barriers live here
    const uint32_t stage0 = base + 1024;            // 3 stages of 32 KB
    const int t = threadIdx.x;
    const int m0 = blockIdx.y * 128;
    const int n0 = blockIdx.x * 64;

    const uint32_t FULLB  = base;        // full[s]  at +8*s
    const uint32_t EMPTYB = base + 24;   // empty[s] at +8*s

    if (t == 0) {
#pragma unroll
        for (int s = 0; s < 3; s++) {
            MBARRIER_INIT(FULLB + 8 * s, 1);
            MBARRIER_INIT(EMPTYB + 8 * s, 256);
        }
    }
    __syncthreads();

    if (t == 0) {   // prologue: fill all 3 stages
#pragma unroll
        for (int s = 0; s < 3; s++)
            issue_stage(stage0 + s * STG, s, m0, n0, FULLB + 8 * s,
                        &mXhi, &mXlo, &mWhi, &mWlo);
    }

    // ---------------- compute setup ----------------
    const int lane = t & 31;
    const int wid = t >> 5;
    const int wm = wid & 1;        // m half (64 rows)
    const int wn = wid >> 1;       // n quarter (32 cols); 0,1 = kv; 2,3 = gate
    const int arow = (lane & 7) | (((lane >> 3) & 1) << 3);
    const int akh = (lane >> 4) & 1;
    const int brow = (lane & 7) | (((lane >> 4) & 1) << 3);
    const int bkh = (lane >> 3) & 1;
    const int rowAb = wm * 64 + arow;
    const int rowBb = wn * 32 + brow;
    const int sA = (rowAb >> 1) & 3;
    const int sB = (rowBb >> 1) & 3;

    float acc[4][4][4];
#pragma unroll
    for (int i = 0; i < 4; i++)
#pragma unroll
        for (int j = 0; j < 4; j++)
#pragma unroll
            for (int q = 0; q < 4; q++) acc[i][j][q] = 0.f;

    // ---------------- main pipeline ----------------
    int slot = 0, ph = 0;
    for (int c = 0; c < CHUNKS; c++) {
        MBARRIER_WAIT_PARITY(FULLB + 8 * slot, ph);

        const uint32_t st = stage0 + slot * STG;
        const uint32_t stAh = st;
        const uint32_t stAl = st + 8192;
        const uint32_t stBh = st + 16384;
        const uint32_t stBl = st + 24576;

#pragma unroll
        for (int ks = 0; ks < 2; ks++) {
            uint32_t bh[2][4], bl[2][4];
            const uint32_t pcA = (uint32_t)(((ks * 2 + akh) ^ sA) << 4);
            const uint32_t pcB = (uint32_t)(((ks * 2 + bkh) ^ sB) << 4);
#pragma unroll
            for (int q = 0; q < 2; q++) {
                const uint32_t ro = (uint32_t)(rowBb + q * 16) * 64 + pcB;
                LDSM4(bh[q], stBh + ro);
                LDSM4(bl[q], stBl + ro);
            }
#pragma unroll
            for (int mf = 0; mf < 4; mf++) {
                uint32_t ah[4], al[4];
                const uint32_t ro = (uint32_t)(rowAb + mf * 16) * 64 + pcA;
                LDSM4(ah, stAh + ro);
                LDSM4(al, stAl + ro);
#pragma unroll
                for (int nf = 0; nf < 4; nf++) {
                    const int q = nf >> 1;
                    const int h = (nf & 1) * 2;
                    MMA16816(acc[mf][nf], ah, bh[q][h], bh[q][h + 1]);
                    MMA16816(acc[mf][nf], ah, bl[q][h], bl[q][h + 1]);
                    MMA16816(acc[mf][nf], al, bh[q][h], bh[q][h + 1]);
                }
            }
        }

        MBARRIER_ARRIVE(EMPTYB + 8 * slot);

        if (t == 0 && c + 3 < CHUNKS) {
            MBARRIER_WAIT_PARITY(EMPTYB + 8 * slot, ph);
            issue_stage(st, c + 3, m0, n0, FULLB + 8 * slot,
                        &mXhi, &mXlo, &mWhi, &mWlo);
        }

        if (++slot == 3) { slot = 0; ph ^= 1; }
    }

    __syncthreads();

    // ---------------- epilogue: gate exchange + store ----------------
    float* sg = reinterpret_cast<float*>(ds + (base - raw) + 1024);  // [128][66]
    const int g  = lane >> 2;
    const int tg = lane & 3;

    if (wn >= 2) {
        const int cb = (wn - 2) * 32;
#pragma unroll
        for (int mf = 0; mf < 4; mf++) {
#pragma unroll
            for (int nf = 0; nf < 4; nf++) {
                const int row0 = wm * 64 + mf * 16 + g;
                const int col = cb + nf * 8 + tg * 2;
                sg[row0 * 66 + col]           = 1.f / (1.f + __expf(-acc[mf][nf][0]));
                sg[row0 * 66 + col + 1]       = 1.f / (1.f + __expf(-acc[mf][nf][1]));
                sg[(row0 + 8) * 66 + col]     = 1.f / (1.f + __expf(-acc[mf][nf][2]));
                sg[(row0 + 8) * 66 + col + 1] = 1.f / (1.f + __expf(-acc[mf][nf][3]));
            }
        }
    }
    __syncthreads();
    if (wn < 2) {
        const int cb = wn * 32;
#pragma unroll
        for (int mf = 0; mf < 4; mf++) {
#pragma unroll
            for (int nf = 0; nf < 4; nf++) {
                const int row0 = wm * 64 + mf * 16 + g;
                const int colw = cb + nf * 8 + tg * 2;
                float2 v0, v1;
                v0.x = acc[mf][nf][0] * sg[row0 * 66 + colw];
                v0.y = acc[mf][nf][1] * sg[row0 * 66 + colw + 1];
                v1.x = acc[mf][nf][2] * sg[(row0 + 8) * 66 + colw];
                v1.y = acc[mf][nf][3] * sg[(row0 + 8) * 66 + colw + 1];
                *reinterpret_cast<float2*>(&g_kvg[(size_t)(m0 + row0) * N_KV + n0 + colw]) = v0;
                *reinterpret_cast<float2*>(&g_kvg[(size_t)(m0 + row0 + 8) * N_KV + n0 + colw]) = v1;
            }
        }
    }
}

// ---------------------------------------------------------------------------
// cp.async GEMM (fallback, R4-validated)
// ---------------------------------------------------------------------------
__global__ void __launch_bounds__(256, 2) gemm_mma() {
    extern __shared__ char ds[];
    const uint32_t sb = smem_u32(ds);
    const int t = threadIdx.x;
    const int m0 = blockIdx.y * 128;
    const int n0 = blockIdx.x * 64;

    const int lr = t >> 2;
    const int lc = t & 3;
    const __nv_bfloat16* pAh  = g_Xhi + (size_t)(m0 + lr) * 4096 + lc * 8;
    const __nv_bfloat16* pAl  = g_Xlo + (size_t)(m0 + lr) * 4096 + lc * 8;
    const __nv_bfloat16* pBhk = g_Whi + (size_t)(n0 + lr) * 4096 + lc * 8;
    const __nv_bfloat16* pBhg = g_Whi + (size_t)(1024 + n0 + lr) * 4096 + lc * 8;
    const __nv_bfloat16* pBlk = g_Wlo + (size_t)(n0 + lr) * 4096 + lc * 8;
    const __nv_bfloat16* pBlg = g_Wlo + (size_t)(1024 + n0 + lr) * 4096 + lc * 8;
    const uint32_t da = lr * 64 + ((lc ^ ((lr >> 1) & 3)) << 4);
    const size_t AROW64 = (size_t)64 * 4096;

    const int lane = t & 31;
    const int wid = t >> 5;
    const int wm = wid & 1;
    const int wn = wid >> 1;
    const int arow = (lane & 7) | (((lane >> 3) & 1) << 3);
    const int akh = (lane >> 4) & 1;
    const int brow = (lane & 7) | (((lane >> 4) & 1) << 3);
    const int bkh = (lane >> 3) & 1;
    const int rowAb = wm * 64 + arow;
    const int rowBb = wn * 32 + brow;
    const int sA = (rowAb >> 1) & 3;
    const int sB = (rowBb >> 1) & 3;

    float acc[4][4][4];
#pragma unroll
    for (int i = 0; i < 4; i++)
#pragma unroll
        for (int j = 0; j < 4; j++)
#pragma unroll
            for (int q = 0; q < 4; q++) acc[i][j][q] = 0.f;

#pragma unroll
    for (int s = 0; s < 2; s++) {
        const uint32_t st = sb + s * STG;
        const size_t k = (size_t)s * 32;
        CP16(st + da,               pAh + k);
        CP16(st + da + 4096,        pAh + k + AROW64);
        CP16(st + 8192 + da,        pAl + k);
        CP16(st + 8192 + da + 4096, pAl + k + AROW64);
        CP16(st + 16384 + da,        pBhk + k);
        CP16(st + 16384 + da + 4096, pBhg + k);
        CP16(st + 24576 + da,        pBlk + k);
        CP16(st + 24576 + da + 4096, pBlg + k);
        CP_COMMIT();
    }

    int slot = 0, wslot = 2;
    for (int c = 0; c < CHUNKS; c++) {
        CP_WAIT1();
        __syncthreads();
        if (c + 2 < CHUNKS) {
            const uint32_t st = sb + wslot * STG;
            const size_t k = (size_t)(c + 2) * 32;
            CP16(st + da,               pAh + k);
            CP16(st + da + 4096,        pAh + k + AROW64);
            CP16(st + 8192 + da,        pAl + k);
            CP16(st + 8192 + da + 4096, pAl + k + AROW64);
            CP16(st + 16384 + da,        pBhk + k);
            CP16(st + 16384 + da + 4096, pBhg + k);
            CP16(st + 24576 + da,        pBlk + k);
            CP16(st + 24576 + da + 4096, pBlg + k);
        }
        CP_COMMIT();

        const uint32_t st = sb + slot * STG;
        const uint32_t stAh = st;
        const uint32_t stAl = st + 8192;
        const uint32_t stBh = st + 16384;
        const uint32_t stBl = st + 24576;

#pragma unroll
        for (int ks = 0; ks < 2; ks++) {
            uint32_t bh[2][4], bl[2][4];
            const uint32_t pcA = (uint32_t)(((ks * 2 + akh) ^ sA) << 4);
            const uint32_t pcB = (uint32_t)(((ks * 2 + bkh) ^ sB) << 4);
#pragma unroll
            for (int q = 0; q < 2; q++) {
                const uint32_t ro = (uint32_t)(rowBb + q * 16) * 64 + pcB;
                LDSM4(bh[q], stBh + ro);
                LDSM4(bl[q], stBl + ro);
            }
#pragma unroll
            for (int mf = 0; mf < 4; mf++) {
                uint32_t ah[4], al[4];
                const uint32_t ro = (uint32_t)(rowAb + mf * 16) * 64 + pcA;
                LDSM4(ah, stAh + ro);
                LDSM4(al, stAl + ro);
#pragma unroll
                for (int nf = 0; nf < 4; nf++) {
                    const int q = nf >> 1;
                    const int h = (nf & 1) * 2;
                    MMA16816(acc[mf][nf], ah, bh[q][h], bh[q][h + 1]);
                    MMA16816(acc[mf][nf], ah, bl[q][h], bl[q][h + 1]);
                    MMA16816(acc[mf][nf], al, bh[q][h], bh[q][h + 1]);
                }
            }
        }
        slot = (slot == 2) ? 0 : slot + 1;
        wslot = (wslot == 2) ? 0 : wslot + 1;
    }

    CP_WAIT0();
    __syncthreads();

    float* sg = reinterpret_cast<float*>(ds);
    const int g  = lane >> 2;
    const int tg = lane & 3;

    if (wn >= 2) {
        const int cb = (wn - 2) * 32;
#pragma unroll
        for (int mf = 0; mf < 4; mf++) {
#pragma unroll
            for (int nf = 0; nf < 4; nf++) {
                const int row0 = wm * 64 + mf * 16 + g;
                const int col = cb + nf * 8 + tg * 2;
                sg[row0 * 66 + col]           = 1.f / (1.f + __expf(-acc[mf][nf][0]));
                sg[row0 * 66 + col + 1]       = 1.f / (1.f + __expf(-acc[mf][nf][1]));
                sg[(row0 + 8) * 66 + col]     = 1.f / (1.f + __expf(-acc[mf][nf][2]));
                sg[(row0 + 8) * 66 + col + 1] = 1.f / (1.f + __expf(-acc[mf][nf][3]));
            }
        }
    }
    __syncthreads();
    if (wn < 2) {
        const int cb = wn * 32;
#pragma unroll
        for (int mf = 0; mf < 4; mf++) {
#pragma unroll
            for (int nf = 0; nf < 4; nf++) {
                const int row0 = wm * 64 + mf * 16 + g;
                const int colw = cb + nf * 8 + tg * 2;
                float2 v0, v1;
                v0.x = acc[mf][nf][0] * sg[row0 * 66 + colw];
                v0.y = acc[mf][nf][1] * sg[row0 * 66 + colw + 1];
                v1.x = acc[mf][nf][2] * sg[(row0 + 8) * 66 + colw];
                v1.y = acc[mf][nf][3] * sg[(row0 + 8) * 66 + colw + 1];
                *reinterpret_cast<float2*>(&g_kvg[(size_t)(m0 + row0) * N_KV + n0 + colw]) = v0;
                *reinterpret_cast<float2*>(&g_kvg[(size_t)(m0 + row0 + 8) * N_KV + n0 + colw]) = v1;
            }
        }
    }
}

// ---------------------------------------------------------------------------
// Combine + RMSNorm + partial RoPE (validated R1)
// ---------------------------------------------------------------------------
__global__ void __launch_bounds__(512) combine_kernel(const float* __restrict__ cosb,
                                                      const float* __restrict__ sinb,
                                                      const float* __restrict__ nw,
                                                      float* __restrict__ out) {
    __shared__ float sh[512];
    __shared__ float wsum[16];
    __shared__ float s_rstd;

    const int d = threadIdx.x;
    const int c = blockIdx.x;
    const int b = blockIdx.y;

    const size_t base = ((size_t)b * S_DIM + (size_t)c * RATIO) * (size_t)N_KV;

    float tacc = 0.f;
    if (c == 0) {
#pragma unroll
        for (int r = 0; r < 4; r++)
            tacc += g_kvg[base + (size_t)r * N_KV + d] * g_w0[r * HD + d];
    } else {
#pragma unroll
        for (int r = 0; r < 4; r++)
            tacc += g_kvg[base + (size_t)r * N_KV + d] * g_w8[r * HD + d];
        const size_t basep = base - (size_t)RATIO * N_KV;
#pragma unroll
        for (int r = 0; r < 4; r++)
            tacc += g_kvg[basep + (size_t)r * N_KV + HD + d] * g_w8[(4 + r) * HD + d];
    }
    sh[d] = tacc;

    float v = tacc * tacc;
#pragma unroll
    for (int off = 16; off; off >>= 1) v += __shfl_xor_sync(0xffffffffu, v, off);
    if ((d & 31) == 0) wsum[d >> 5] = v;
    __syncthreads();
    if (d == 0) {
        float s = 0.f;
#pragma unroll
        for (int w = 0; w < 16; w++) s += wsum[w];
        s_rstd = rsqrtf(s * (1.f / (float)HD) + 1e-6f);
    }
    __syncthreads();
    const float rstd = s_rstd;

    float o;
    if (d < HD - ROPE_D) {
        o = sh[d] * rstd * nw[d];
    } else {
        const int p  = (d - (HD - ROPE_D)) >> 1;
        const int de = (HD - ROPE_D) + 2 * p;
        const int dq = de + 1;
        const float e  = sh[de] * rstd * nw[de];
        const float oo = sh[dq] * rstd * nw[dq];
        const size_t ci = ((size_t)b * C_DIM + c) * (ROPE_D / 2) + p;
        const float cv = cosb[ci];
        const float sv = sinb[ci];
        o = ((d & 1) == 0) ? (e * cv - oo * sv) : (e * sv + oo * cv);
    }
    out[((size_t)b * C_DIM + c) * HD + d] = o;
}

// ---------------------------------------------------------------------------
// Launch
// ---------------------------------------------------------------------------
typedef CUresult (CUDAAPI *PFN_tmEncode)(
    CUtensorMap*, CUtensorMapDataType, cuuint32_t, void*,
    const cuuint64_t*, const cuuint64_t*, const cuuint32_t*, const cuuint32_t*,
    CUtensorMapInterleave, CUtensorMapSwizzle, CUtensorMapL2promotion,
    CUtensorMapFloatOOBfill);

extern "C" void kernel_launch(void* const* d_in, const int* in_sizes, int n_in,
                              void* d_out, int out_size) {
    const float* x    = (const float*)d_in[0];
    const float* cosb = (const float*)d_in[1];
    const float* sinb = (const float*)d_in[2];
    const float* Wkv  = (const float*)d_in[3];
    const float* Wg   = (const float*)d_in[4];
    const float* ape  = (const float*)d_in[5];
    const float* nw   = (const float*)d_in[6];
    float* out = (float*)d_out;

    // Encode tensormaps (SW64 matches the manual chunk^((row>>1)&3) swizzle)
    bool tc_ok = false;
    CUtensorMap mXhi{}, mXlo{}, mWhi{}, mWlo{};
    {
        void* fp = nullptr;
        cudaDriverEntryPointQueryResult qr;
        PFN_tmEncode enc = nullptr;
        if (cudaGetDriverEntryPoint("cuTensorMapEncodeTiled", &fp,
                                    cudaEnableDefault, &qr) == cudaSuccess && fp)
            enc = (PFN_tmEncode)fp;
        if (enc) {
            void *pxh = nullptr, *pxl = nullptr, *pwh = nullptr, *pwl = nullptr;
            cudaGetSymbolAddress(&pxh, g_Xhi);
            cudaGetSymbolAddress(&pxl, g_Xlo);
            cudaGetSymbolAddress(&pwh, g_Whi);
            cudaGetSymbolAddress(&pwl, g_Wlo);
            if (pxh && pxl && pwh && pwl) {
                cuuint64_t dX[2] = {K_TOT, M_TOT};
                cuuint64_t sX[1] = {K_TOT * 2};
                cuuint64_t dW[2] = {K_TOT, 2048};
                cuuint64_t sW[1] = {K_TOT * 2};
                cuuint32_t boxX[2] = {32, 128};
                cuuint32_t boxW[2] = {32, 64};
                cuuint32_t es[2]  = {1, 1};
                CUresult r;
                r = enc(&mXhi, CU_TENSOR_MAP_DATA_TYPE_BFLOAT16, 2, pxh, dX, sX, boxX, es,
                        CU_TENSOR_MAP_INTERLEAVE_NONE, CU_TENSOR_MAP_SWIZZLE_64B,
                        CU_TENSOR_MAP_L2_PROMOTION_L2_128B, CU_TENSOR_MAP_FLOAT_OOB_FILL_NONE);
                if (r == CUDA_SUCCESS)
                    r = enc(&mXlo, CU_TENSOR_MAP_DATA_TYPE_BFLOAT16, 2, pxl, dX, sX, boxX, es,
                            CU_TENSOR_MAP_INTERLEAVE_NONE, CU_TENSOR_MAP_SWIZZLE_64B,
                            CU_TENSOR_MAP_L2_PROMOTION_L2_128B, CU_TENSOR_MAP_FLOAT_OOB_FILL_NONE);
                if (r == CUDA_SUCCESS)
                    r = enc(&mWhi, CU_TENSOR_MAP_DATA_TYPE_BFLOAT16, 2, pwh, dW, sW, boxW, es,
                            CU_TENSOR_MAP_INTERLEAVE_NONE, CU_TENSOR_MAP_SWIZZLE_64B,
                            CU_TENSOR_MAP_L2_PROMOTION_L2_128B, CU_TENSOR_MAP_FLOAT_OOB_FILL_NONE);
                if (r == CUDA_SUCCESS)
                    r = enc(&mWlo, CU_TENSOR_MAP_DATA_TYPE_BFLOAT16, 2, pwl, dW, sW, boxW, es,
                            CU_TENSOR_MAP_INTERLEAVE_NONE, CU_TENSOR_MAP_SWIZZLE_64B,
                            CU_TENSOR_MAP_L2_PROMOTION_L2_128B, CU_TENSOR_MAP_FLOAT_OOB_FILL_NONE);
                if (r == CUDA_SUCCESS &&
                    cudaFuncSetAttribute(gemm_tma,
                                         cudaFuncAttributeMaxDynamicSharedMemorySize,
                                         SMEM_TMA) == cudaSuccess)
                    tc_ok = true;
            }
        }
    }

    weights_kernel<<<1, 512>>>(ape);
    convX_kernel<<<65536, 256>>>((const float4*)x);
    convW_kernel<<<8192, 256>>>(Wkv, Wg);

    if (tc_ok) {
        gemm_tma<<<dim3(16, 128), 256, SMEM_TMA>>>(mXhi, mXlo, mWhi, mWlo);
    } else {
        cudaFuncSetAttribute(gemm_mma, cudaFuncAttributeMaxDynamicSharedMemorySize, SMEM_CPA);
        gemm_mma<<<dim3(16, 128), 256, SMEM_CPA>>>();
    }

    combine_kernel<<<dim3(C_DIM, B_DIM), 512>>>(cosb, sinb, nw, out);
}

// round 7
// speedup vs baseline: 6.5907x; 1.4183x over previous
#include <cuda.h>
#include <cuda_runtime.h>
#include <cuda_bf16.h>
#include <cstdint>

// ---------------------------------------------------------------------------
// Problem constants
// ---------------------------------------------------------------------------
#define B_DIM   4
#define S_DIM   4096
#define H_DIM   4096
#define HD      512
#define ROPE_D  64
#define RATIO   4
#define C_DIM   (S_DIM / RATIO)          // 1024
#define M_TOT   (B_DIM * S_DIM)          // 16384
#define K_TOT   H_DIM                    // 4096
#define N_KV    (2 * HD)                 // 1024

// ---------------------------------------------------------------------------
// Device scratch
// ---------------------------------------------------------------------------
__device__ __align__(16) float           g_kvg[(size_t)M_TOT * N_KV];   // 64 MiB
__device__ __align__(16) float           g_w8[8 * HD];
__device__ __align__(16) float           g_w0[4 * HD];
// tf32 path (primary)
__device__ __align__(1024) float         g_Xtf[(size_t)M_TOT * K_TOT];  // 256 MiB
__device__ __align__(1024) float         g_Wtf[(size_t)2048 * K_TOT];   // 32 MiB (rows 0-1023 kv, 1024-2047 gate)
// bf16 path (fallback)
__device__ __align__(1024) __nv_bfloat16 g_Xhi[(size_t)M_TOT * K_TOT];
__device__ __align__(1024) __nv_bfloat16 g_Xlo[(size_t)M_TOT * K_TOT];
__device__ __align__(1024) __nv_bfloat16 g_Whi[(size_t)2048 * K_TOT];
__device__ __align__(1024) __nv_bfloat16 g_Wlo[(size_t)2048 * K_TOT];

// ---------------------------------------------------------------------------
// PTX helpers (plain sm_90-level features only; no 'a'-suffix instructions)
// ---------------------------------------------------------------------------
__device__ __forceinline__ uint32_t smem_u32(const void* p) {
    uint32_t a;
    asm("{ .reg .u64 t; cvta.to.shared.u64 t, %1; cvt.u32.u64 %0, t; }"
        : "=r"(a) : "l"(p));
    return a;
}
__device__ __forceinline__ uint32_t tf32r(float f) {
    uint32_t r;
    asm("cvt.rna.tf32.f32 %0, %1;" : "=r"(r) : "f"(f));
    return r;
}

#define CP16(s, g) \
    asm volatile("cp.async.cg.shared.global [%0], [%1], 16;" :: "r"(s), "l"(g))
#define CP_COMMIT()  asm volatile("cp.async.commit_group;" ::: "memory")
#define CP_WAIT1()   asm volatile("cp.async.wait_group 1;" ::: "memory")
#define CP_WAIT0()   asm volatile("cp.async.wait_group 0;" ::: "memory")

#define LDSM4(r, addr) \
    asm volatile("ldmatrix.sync.aligned.m8n8.x4.shared.b16 {%0,%1,%2,%3}, [%4];" \
                 : "=r"((r)[0]), "=r"((r)[1]), "=r"((r)[2]), "=r"((r)[3]) : "r"(addr))

#define MMA16816(d, a, b0, b1) \
    asm volatile("mma.sync.aligned.m16n8k16.row.col.f32.bf16.bf16.f32 " \
                 "{%0,%1,%2,%3}, {%4,%5,%6,%7}, {%8,%9}, {%0,%1,%2,%3};" \
                 : "+f"((d)[0]), "+f"((d)[1]), "+f"((d)[2]), "+f"((d)[3]) \
                 : "r"((a)[0]), "r"((a)[1]), "r"((a)[2]), "r"((a)[3]), \
                   "r"(b0), "r"(b1))

#define MMATF32(d, a, b0, b1) \
    asm volatile("mma.sync.aligned.m16n8k8.row.col.f32.tf32.tf32.f32 " \
                 "{%0,%1,%2,%3}, {%4,%5,%6,%7}, {%8,%9}, {%0,%1,%2,%3};" \
                 : "+f"((d)[0]), "+f"((d)[1]), "+f"((d)[2]), "+f"((d)[3]) \
                 : "r"((a)[0]), "r"((a)[1]), "r"((a)[2]), "r"((a)[3]), \
                   "r"(b0), "r"(b1))

#define MBARRIER_INIT(addr, cnt) \
    asm volatile("mbarrier.init.shared.b64 [%0], %1;" :: "r"((uint32_t)(addr)), "r"((uint32_t)(cnt)) : "memory")
#define MBARRIER_ARRIVE(addr) \
    asm volatile("mbarrier.arrive.shared.b64 _, [%0];" :: "r"((uint32_t)(addr)) : "memory")
#define MBARRIER_EXPECT_TX(addr, bytes) \
    asm volatile("mbarrier.arrive.expect_tx.shared.b64 _, [%0], %1;" :: "r"((uint32_t)(addr)), "r"((uint32_t)(bytes)) : "memory")
#define MBARRIER_WAIT_PARITY(addr, parity) do {                                   \
    uint32_t _mb = (uint32_t)(addr);                                              \
    uint32_t _ph = (uint32_t)(parity);                                            \
    asm volatile(                                                                 \
        "{\n\t.reg .pred P1;\n\t"                                                 \
        "WAIT_LOOP_%=:\n\t"                                                       \
        "mbarrier.try_wait.parity.acquire.cta.shared::cta.b64 P1, [%0], %1, 0x989680;\n\t" \
        "@P1 bra.uni WAIT_DONE_%=;\n\t"                                           \
        "bra.uni WAIT_LOOP_%=;\n\t"                                               \
        "WAIT_DONE_%=:\n\t}"                                                      \
        :: "r"(_mb), "r"(_ph) : "memory");                                        \
} while (0)

#define TMA2D(smem_addr, map_ptr, cx, cy, mbar) \
    asm volatile("cp.async.bulk.tensor.2d.shared::cta.global.tile.mbarrier::complete_tx::bytes " \
                 "[%0], [%1, {%2, %3}], [%4];"                                    \
                 :: "r"((uint32_t)(smem_addr)), "l"(map_ptr),                     \
                    "r"((int32_t)(cx)), "r"((int32_t)(cy)),                       \
                    "r"((uint32_t)(mbar)) : "memory")

// ---------------------------------------------------------------------------
// Kernel: ape -> softmax weight tables
// ---------------------------------------------------------------------------
__global__ void weights_kernel(const float* __restrict__ ape) {
    int d = threadIdx.x;  // 0..511
    float v[8];
#pragma unroll
    for (int r = 0; r < 4; r++) {
        v[r]     = ape[r * 1024 + d];
        v[4 + r] = ape[r * 1024 + 512 + d];
    }
    float m4 = v[0];
#pragma unroll
    for (int i = 1; i < 4; i++) m4 = fmaxf(m4, v[i]);
    float e4[4]; float s4 = 0.f;
#pragma unroll
    for (int i = 0; i < 4; i++) { e4[i] = expf(v[i] - m4); s4 += e4[i]; }
    float inv4 = 1.f / s4;
#pragma unroll
    for (int i = 0; i < 4; i++) g_w0[i * HD + d] = e4[i] * inv4;
    float m8 = v[0];
#pragma unroll
    for (int i = 1; i < 8; i++) m8 = fmaxf(m8, v[i]);
    float e8[8]; float s8 = 0.f;
#pragma unroll
    for (int i = 0; i < 8; i++) { e8[i] = expf(v[i] - m8); s8 += e8[i]; }
    float inv8 = 1.f / s8;
#pragma unroll
    for (int i = 0; i < 8; i++) g_w8[i * HD + d] = e8[i] * inv8;
}

// ---------------------------------------------------------------------------
// tf32 conversion kernels (primary path)
// ---------------------------------------------------------------------------
__global__ void __launch_bounds__(256) convXtf(const float4* __restrict__ x) {
    size_t i = (size_t)blockIdx.x * 256 + threadIdx.x;   // 16,777,216 float4
    float4 v = x[i];
    uint4 o;
    o.x = tf32r(v.x); o.y = tf32r(v.y); o.z = tf32r(v.z); o.w = tf32r(v.w);
    reinterpret_cast<uint4*>(g_Xtf)[i] = o;
}

__global__ void __launch_bounds__(256) convWtf(const float* __restrict__ wkv,
                                               const float* __restrict__ wg) {
    size_t i = (size_t)blockIdx.x * 256 + threadIdx.x;   // 2,097,152 float4
    size_t e0 = i * 4;
    size_t row = e0 >> 12;
    size_t k = e0 & 4095;
    const float* src = (row < 1024) ? (wkv + row * 4096 + k)
                                    : (wg + (row - 1024) * 4096 + k);
    float4 v = *reinterpret_cast<const float4*>(src);
    uint4 o;
    o.x = tf32r(v.x); o.y = tf32r(v.y); o.z = tf32r(v.z); o.w = tf32r(v.w);
    reinterpret_cast<uint4*>(g_Wtf)[i] = o;
}

// ---------------------------------------------------------------------------
// bf16 conversion kernels (fallback path)
// ---------------------------------------------------------------------------
__device__ __forceinline__ unsigned pk_bf2(float a, float b, float& ra, float& rb) {
    __nv_bfloat16 ha = __float2bfloat16_rn(a);
    __nv_bfloat16 hb = __float2bfloat16_rn(b);
    ra = a - __bfloat162float(ha);
    rb = b - __bfloat162float(hb);
    __nv_bfloat162 t(ha, hb);
    return *reinterpret_cast<unsigned*>(&t);
}
__device__ __forceinline__ unsigned pk_lo(float a, float b) {
    __nv_bfloat162 t(__float2bfloat16_rn(a), __float2bfloat16_rn(b));
    return *reinterpret_cast<unsigned*>(&t);
}

__global__ void __launch_bounds__(256) convX_kernel(const float4* __restrict__ x) {
    size_t i = (size_t)blockIdx.x * 256 + threadIdx.x;
    float4 v = x[i];
    float rx, ry, rz, rw;
    uint2 H, L;
    H.x = pk_bf2(v.x, v.y, rx, ry);
    H.y = pk_bf2(v.z, v.w, rz, rw);
    L.x = pk_lo(rx, ry);
    L.y = pk_lo(rz, rw);
    reinterpret_cast<uint2*>(g_Xhi)[i] = H;
    reinterpret_cast<uint2*>(g_Xlo)[i] = L;
}

__global__ void __launch_bounds__(256) convW_kernel(const float* __restrict__ wkv,
                                                    const float* __restrict__ wg) {
    size_t i = (size_t)blockIdx.x * 256 + threadIdx.x;
    size_t e0 = i * 4;
    size_t row = e0 >> 12;
    size_t k = e0 & 4095;
    const float* src = (row < 1024) ? (wkv + row * 4096 + k)
                                    : (wg + (row - 1024) * 4096 + k);
    float4 v = *reinterpret_cast<const float4*>(src);
    float rx, ry, rz, rw;
    uint2 H, L;
    H.x = pk_bf2(v.x, v.y, rx, ry);
    H.y = pk_bf2(v.z, v.w, rz, rw);
    L.x = pk_lo(rx, ry);
    L.y = pk_lo(rz, rw);
    reinterpret_cast<uint2*>(g_Whi)[i] = H;
    reinterpret_cast<uint2*>(g_Wlo)[i] = L;
}

// ---------------------------------------------------------------------------
// tf32 TMA GEMM (primary): CTA = 128 M x (64 kv + 64 gate), K in 128 chunks
// of 32. Stage (32 KB): A[128 rows x 128 B] + B[128 rows x 128 B]
// (B rows 0-63 kv, 64-127 gate). SW128: phys 16B-chunk = c ^ (row & 7).
// ---------------------------------------------------------------------------
#define NST      3
#define STG      32768
#define CHUNKS   128
#define SMEM_TMA (2048 + NST * STG)
#define SMEM_CPA (NST * STG)

__device__ __forceinline__ void issue_stage_tf(
    uint32_t st, int c, int m0, int n0, uint32_t fullb,
    const CUtensorMap* mX, const CUtensorMap* mW)
{
    const int k0 = c * 32;
    MBARRIER_EXPECT_TX(fullb, STG);
    TMA2D(st +     0, mX, k0, m0,        fullb);   // A: 128 rows x 128 B
    TMA2D(st + 16384, mW, k0, n0,        fullb);   // B kv: 64 rows
    TMA2D(st + 24576, mW, k0, 1024 + n0, fullb);   // B gate: 64 rows
}

__global__ void __launch_bounds__(256, 2) gemm_tf(
    const __grid_constant__ CUtensorMap mX,
    const __grid_constant__ CUtensorMap mW)
{
    extern __shared__ char ds[];
    const uint32_t raw  = smem_u32(ds);
    const uint32_t base = (raw + 1023u) & ~1023u;
    const uint32_t stage0 = base + 1024;
    const int t = threadIdx.x;
    const int m0 = blockIdx.y * 128;
    const int n0 = blockIdx.x * 64;

    const uint32_t FULLB  = base;
    const uint32_t EMPTYB = base + 24;

    if (t == 0) {
#pragma unroll
        for (int s = 0; s < 3; s++) {
            MBARRIER_INIT(FULLB + 8 * s, 1);
            MBARRIER_INIT(EMPTYB + 8 * s, 256);
        }
    }
    __syncthreads();

    if (t == 0) {
#pragma unroll
        for (int s = 0; s < 3; s++)
            issue_stage_tf(stage0 + s * STG, s, m0, n0, FULLB + 8 * s, &mX, &mW);
    }

    // compute setup (b16-view fragment mapping; identical lane layout to bf16)
    const int lane = t & 31;
    const int wid = t >> 5;
    const int wm = wid & 1;        // m half (64 rows)
    const int wn = wid >> 1;       // n quarter (32 cols); 0,1 = kv; 2,3 = gate
    const int arow = (lane & 7) | (((lane >> 3) & 1) << 3);
    const int akh = (lane >> 4) & 1;
    const int brow = (lane & 7) | (((lane >> 4) & 1) << 3);
    const int bkh = (lane >> 3) & 1;
    const int rowAb = wm * 64 + arow;
    const int rowBb = wn * 32 + brow;
    const int sA = rowAb & 7;
    const int sB = rowBb & 7;

    float acc[4][4][4];
#pragma unroll
    for (int i = 0; i < 4; i++)
#pragma unroll
        for (int j = 0; j < 4; j++)
#pragma unroll
            for (int q = 0; q < 4; q++) acc[i][j][q] = 0.f;

    int slot = 0, ph = 0;
    for (int c = 0; c < CHUNKS; c++) {
        MBARRIER_WAIT_PARITY(FULLB + 8 * slot, ph);

        const uint32_t stA = stage0 + slot * STG;
        const uint32_t stB = stA + 16384;

#pragma unroll
        for (int ks = 0; ks < 4; ks++) {   // 4 x k8 per 32-K chunk
            uint32_t bb[2][4];
            const uint32_t pcA = (uint32_t)(((2 * ks + akh) ^ sA) << 4);
            const uint32_t pcB = (uint32_t)(((2 * ks + bkh) ^ sB) << 4);
#pragma unroll
            for (int q = 0; q < 2; q++) {
                const uint32_t ro = (uint32_t)(rowBb + q * 16) * 128 + pcB;
                LDSM4(bb[q], stB + ro);
            }
#pragma unroll
            for (int mf = 0; mf < 4; mf++) {
                uint32_t a[4];
                const uint32_t ro = (uint32_t)(rowAb + mf * 16) * 128 + pcA;
                LDSM4(a, stA + ro);
#pragma unroll
                for (int nf = 0; nf < 4; nf++) {
                    const int q = nf >> 1;
                    const int h = (nf & 1) * 2;
                    MMATF32(acc[mf][nf], a, bb[q][h], bb[q][h + 1]);
                }
            }
        }

        MBARRIER_ARRIVE(EMPTYB + 8 * slot);

        if (t == 0 && c + 3 < CHUNKS) {
            MBARRIER_WAIT_PARITY(EMPTYB + 8 * slot, ph);
            issue_stage_tf(stA, c + 3, m0, n0, FULLB + 8 * slot, &mX, &mW);
        }

        if (++slot == 3) { slot = 0; ph ^= 1; }
    }

    __syncthreads();

    // epilogue: gate exchange + store
    float* sg = reinterpret_cast<float*>(ds + (base - raw) + 1024);  // [128][66]
    const int g  = lane >> 2;
    const int tg = lane & 3;

    if (wn >= 2) {
        const int cb = (wn - 2) * 32;
#pragma unroll
        for (int mf = 0; mf < 4; mf++) {
#pragma unroll
            for (int nf = 0; nf < 4; nf++) {
                const int row0 = wm * 64 + mf * 16 + g;
                const int col = cb + nf * 8 + tg * 2;
                sg[row0 * 66 + col]           = 1.f / (1.f + __expf(-acc[mf][nf][0]));
                sg[row0 * 66 + col + 1]       = 1.f / (1.f + __expf(-acc[mf][nf][1]));
                sg[(row0 + 8) * 66 + col]     = 1.f / (1.f + __expf(-acc[mf][nf][2]));
                sg[(row0 + 8) * 66 + col + 1] = 1.f / (1.f + __expf(-acc[mf][nf][3]));
            }
        }
    }
    __syncthreads();
    if (wn < 2) {
        const int cb = wn * 32;
#pragma unroll
        for (int mf = 0; mf < 4; mf++) {
#pragma unroll
            for (int nf = 0; nf < 4; nf++) {
                const int row0 = wm * 64 + mf * 16 + g;
                const int colw = cb + nf * 8 + tg * 2;
                float2 v0, v1;
                v0.x = acc[mf][nf][0] * sg[row0 * 66 + colw];
                v0.y = acc[mf][nf][1] * sg[row0 * 66 + colw + 1];
                v1.x = acc[mf][nf][2] * sg[(row0 + 8) * 66 + colw];
                v1.y = acc[mf][nf][3] * sg[(row0 + 8) * 66 + colw + 1];
                *reinterpret_cast<float2*>(&g_kvg[(size_t)(m0 + row0) * N_KV + n0 + colw]) = v0;
                *reinterpret_cast<float2*>(&g_kvg[(size_t)(m0 + row0 + 8) * N_KV + n0 + colw]) = v1;
            }
        }
    }
}

// ---------------------------------------------------------------------------
// bf16 cp.async GEMM (fallback, R4-validated)
// ---------------------------------------------------------------------------
__global__ void __launch_bounds__(256, 2) gemm_mma() {
    extern __shared__ char ds[];
    const uint32_t sb = smem_u32(ds);
    const int t = threadIdx.x;
    const int m0 = blockIdx.y * 128;
    const int n0 = blockIdx.x * 64;

    const int lr = t >> 2;
    const int lc = t & 3;
    const __nv_bfloat16* pAh  = g_Xhi + (size_t)(m0 + lr) * 4096 + lc * 8;
    const __nv_bfloat16* pAl  = g_Xlo + (size_t)(m0 + lr) * 4096 + lc * 8;
    const __nv_bfloat16* pBhk = g_Whi + (size_t)(n0 + lr) * 4096 + lc * 8;
    const __nv_bfloat16* pBhg = g_Whi + (size_t)(1024 + n0 + lr) * 4096 + lc * 8;
    const __nv_bfloat16* pBlk = g_Wlo + (size_t)(n0 + lr) * 4096 + lc * 8;
    const __nv_bfloat16* pBlg = g_Wlo + (size_t)(1024 + n0 + lr) * 4096 + lc * 8;
    const uint32_t da = lr * 64 + ((lc ^ ((lr >> 1) & 3)) << 4);
    const size_t AROW64 = (size_t)64 * 4096;

    const int lane = t & 31;
    const int wid = t >> 5;
    const int wm = wid & 1;
    const int wn = wid >> 1;
    const int arow = (lane & 7) | (((lane >> 3) & 1) << 3);
    const int akh = (lane >> 4) & 1;
    const int brow = (lane & 7) | (((lane >> 4) & 1) << 3);
    const int bkh = (lane >> 3) & 1;
    const int rowAb = wm * 64 + arow;
    const int rowBb = wn * 32 + brow;
    const int sA = (rowAb >> 1) & 3;
    const int sB = (rowBb >> 1) & 3;

    float acc[4][4][4];
#pragma unroll
    for (int i = 0; i < 4; i++)
#pragma unroll
        for (int j = 0; j < 4; j++)
#pragma unroll
            for (int q = 0; q < 4; q++) acc[i][j][q] = 0.f;

#pragma unroll
    for (int s = 0; s < 2; s++) {
        const uint32_t st = sb + s * STG;
        const size_t k = (size_t)s * 32;
        CP16(st + da,               pAh + k);
        CP16(st + da + 4096,        pAh + k + AROW64);
        CP16(st + 8192 + da,        pAl + k);
        CP16(st + 8192 + da + 4096, pAl + k + AROW64);
        CP16(st + 16384 + da,        pBhk + k);
        CP16(st + 16384 + da + 4096, pBhg + k);
        CP16(st + 24576 + da,        pBlk + k);
        CP16(st + 24576 + da + 4096, pBlg + k);
        CP_COMMIT();
    }

    int slot = 0, wslot = 2;
    for (int c = 0; c < CHUNKS; c++) {
        CP_WAIT1();
        __syncthreads();
        if (c + 2 < CHUNKS) {
            const uint32_t st = sb + wslot * STG;
            const size_t k = (size_t)(c + 2) * 32;
            CP16(st + da,               pAh + k);
            CP16(st + da + 4096,        pAh + k + AROW64);
            CP16(st + 8192 + da,        pAl + k);
            CP16(st + 8192 + da + 4096, pAl + k + AROW64);
            CP16(st + 16384 + da,        pBhk + k);
            CP16(st + 16384 + da + 4096, pBhg + k);
            CP16(st + 24576 + da,        pBlk + k);
            CP16(st + 24576 + da + 4096, pBlg + k);
        }
        CP_COMMIT();

        const uint32_t st = sb + slot * STG;
        const uint32_t stAh = st;
        const uint32_t stAl = st + 8192;
        const uint32_t stBh = st + 16384;
        const uint32_t stBl = st + 24576;

#pragma unroll
        for (int ks = 0; ks < 2; ks++) {
            uint32_t bh[2][4], bl[2][4];
            const uint32_t pcA = (uint32_t)(((ks * 2 + akh) ^ sA) << 4);
            const uint32_t pcB = (uint32_t)(((ks * 2 + bkh) ^ sB) << 4);
#pragma unroll
            for (int q = 0; q < 2; q++) {
                const uint32_t ro = (uint32_t)(rowBb + q * 16) * 64 + pcB;
                LDSM4(bh[q], stBh + ro);
                LDSM4(bl[q], stBl + ro);
            }
#pragma unroll
            for (int mf = 0; mf < 4; mf++) {
                uint32_t ah[4], al[4];
                const uint32_t ro = (uint32_t)(rowAb + mf * 16) * 64 + pcA;
                LDSM4(ah, stAh + ro);
                LDSM4(al, stAl + ro);
#pragma unroll
                for (int nf = 0; nf < 4; nf++) {
                    const int q = nf >> 1;
                    const int h = (nf & 1) * 2;
                    MMA16816(acc[mf][nf], ah, bh[q][h], bh[q][h + 1]);
                    MMA16816(acc[mf][nf], ah, bl[q][h], bl[q][h + 1]);
                    MMA16816(acc[mf][nf], al, bh[q][h], bh[q][h + 1]);
                }
            }
        }
        slot = (slot == 2) ? 0 : slot + 1;
        wslot = (wslot == 2) ? 0 : wslot + 1;
    }

    CP_WAIT0();
    __syncthreads();

    float* sg = reinterpret_cast<float*>(ds);
    const int g  = lane >> 2;
    const int tg = lane & 3;

    if (wn >= 2) {
        const int cb = (wn - 2) * 32;
#pragma unroll
        for (int mf = 0; mf < 4; mf++) {
#pragma unroll
            for (int nf = 0; nf < 4; nf++) {
                const int row0 = wm * 64 + mf * 16 + g;
                const int col = cb + nf * 8 + tg * 2;
                sg[row0 * 66 + col]           = 1.f / (1.f + __expf(-acc[mf][nf][0]));
                sg[row0 * 66 + col + 1]       = 1.f / (1.f + __expf(-acc[mf][nf][1]));
                sg[(row0 + 8) * 66 + col]     = 1.f / (1.f + __expf(-acc[mf][nf][2]));
                sg[(row0 + 8) * 66 + col + 1] = 1.f / (1.f + __expf(-acc[mf][nf][3]));
            }
        }
    }
    __syncthreads();
    if (wn < 2) {
        const int cb = wn * 32;
#pragma unroll
        for (int mf = 0; mf < 4; mf++) {
#pragma unroll
            for (int nf = 0; nf < 4; nf++) {
                const int row0 = wm * 64 + mf * 16 + g;
                const int colw = cb + nf * 8 + tg * 2;
                float2 v0, v1;
                v0.x = acc[mf][nf][0] * sg[row0 * 66 + colw];
                v0.y = acc[mf][nf][1] * sg[row0 * 66 + colw + 1];
                v1.x = acc[mf][nf][2] * sg[(row0 + 8) * 66 + colw];
                v1.y = acc[mf][nf][3] * sg[(row0 + 8) * 66 + colw + 1];
                *reinterpret_cast<float2*>(&g_kvg[(size_t)(m0 + row0) * N_KV + n0 + colw]) = v0;
                *reinterpret_cast<float2*>(&g_kvg[(size_t)(m0 + row0 + 8) * N_KV + n0 + colw]) = v1;
            }
        }
    }
}

// ---------------------------------------------------------------------------
// Combine + RMSNorm + partial RoPE (validated R1)
// ---------------------------------------------------------------------------
__global__ void __launch_bounds__(512) combine_kernel(const float* __restrict__ cosb,
                                                      const float* __restrict__ sinb,
                                                      const float* __restrict__ nw,
                                                      float* __restrict__ out) {
    __shared__ float sh[512];
    __shared__ float wsum[16];
    __shared__ float s_rstd;

    const int d = threadIdx.x;
    const int c = blockIdx.x;
    const int b = blockIdx.y;

    const size_t base = ((size_t)b * S_DIM + (size_t)c * RATIO) * (size_t)N_KV;

    float tacc = 0.f;
    if (c == 0) {
#pragma unroll
        for (int r = 0; r < 4; r++)
            tacc += g_kvg[base + (size_t)r * N_KV + d] * g_w0[r * HD + d];
    } else {
#pragma unroll
        for (int r = 0; r < 4; r++)
            tacc += g_kvg[base + (size_t)r * N_KV + d] * g_w8[r * HD + d];
        const size_t basep = base - (size_t)RATIO * N_KV;
#pragma unroll
        for (int r = 0; r < 4; r++)
            tacc += g_kvg[basep + (size_t)r * N_KV + HD + d] * g_w8[(4 + r) * HD + d];
    }
    sh[d] = tacc;

    float v = tacc * tacc;
#pragma unroll
    for (int off = 16; off; off >>= 1) v += __shfl_xor_sync(0xffffffffu, v, off);
    if ((d & 31) == 0) wsum[d >> 5] = v;
    __syncthreads();
    if (d == 0) {
        float s = 0.f;
#pragma unroll
        for (int w = 0; w < 16; w++) s += wsum[w];
        s_rstd = rsqrtf(s * (1.f / (float)HD) + 1e-6f);
    }
    __syncthreads();
    const float rstd = s_rstd;

    float o;
    if (d < HD - ROPE_D) {
        o = sh[d] * rstd * nw[d];
    } else {
        const int p  = (d - (HD - ROPE_D)) >> 1;
        const int de = (HD - ROPE_D) + 2 * p;
        const int dq = de + 1;
        const float e  = sh[de] * rstd * nw[de];
        const float oo = sh[dq] * rstd * nw[dq];
        const size_t ci = ((size_t)b * C_DIM + c) * (ROPE_D / 2) + p;
        const float cv = cosb[ci];
        const float sv = sinb[ci];
        o = ((d & 1) == 0) ? (e * cv - oo * sv) : (e * sv + oo * cv);
    }
    out[((size_t)b * C_DIM + c) * HD + d] = o;
}

// ---------------------------------------------------------------------------
// Launch
// ---------------------------------------------------------------------------
typedef CUresult (CUDAAPI *PFN_tmEncode)(
    CUtensorMap*, CUtensorMapDataType, cuuint32_t, void*,
    const cuuint64_t*, const cuuint64_t*, const cuuint32_t*, const cuuint32_t*,
    CUtensorMapInterleave, CUtensorMapSwizzle, CUtensorMapL2promotion,
    CUtensorMapFloatOOBfill);

extern "C" void kernel_launch(void* const* d_in, const int* in_sizes, int n_in,
                              void* d_out, int out_size) {
    const float* x    = (const float*)d_in[0];
    const float* cosb = (const float*)d_in[1];
    const float* sinb = (const float*)d_in[2];
    const float* Wkv  = (const float*)d_in[3];
    const float* Wg   = (const float*)d_in[4];
    const float* ape  = (const float*)d_in[5];
    const float* nw   = (const float*)d_in[6];
    float* out = (float*)d_out;

    bool tc_ok = false;
    CUtensorMap mX{}, mW{};
    {
        void* fp = nullptr;
        cudaDriverEntryPointQueryResult qr;
        PFN_tmEncode enc = nullptr;
        if (cudaGetDriverEntryPoint("cuTensorMapEncodeTiled", &fp,
                                    cudaEnableDefault, &qr) == cudaSuccess && fp)
            enc = (PFN_tmEncode)fp;
        if (enc) {
            void *px = nullptr, *pw = nullptr;
            cudaGetSymbolAddress(&px, g_Xtf);
            cudaGetSymbolAddress(&pw, g_Wtf);
            if (px && pw) {
                cuuint64_t dX[2] = {K_TOT, M_TOT};
                cuuint64_t sX[1] = {K_TOT * 4};
                cuuint64_t dW[2] = {K_TOT, 2048};
                cuuint64_t sW[1] = {K_TOT * 4};
                cuuint32_t boxX[2] = {32, 128};
                cuuint32_t boxW[2] = {32, 64};
                cuuint32_t es[2]  = {1, 1};
                CUresult r;
                r = enc(&mX, CU_TENSOR_MAP_DATA_TYPE_FLOAT32, 2, px, dX, sX, boxX, es,
                        CU_TENSOR_MAP_INTERLEAVE_NONE, CU_TENSOR_MAP_SWIZZLE_128B,
                        CU_TENSOR_MAP_L2_PROMOTION_L2_128B, CU_TENSOR_MAP_FLOAT_OOB_FILL_NONE);
                if (r == CUDA_SUCCESS)
                    r = enc(&mW, CU_TENSOR_MAP_DATA_TYPE_FLOAT32, 2, pw, dW, sW, boxW, es,
                            CU_TENSOR_MAP_INTERLEAVE_NONE, CU_TENSOR_MAP_SWIZZLE_128B,
                            CU_TENSOR_MAP_L2_PROMOTION_L2_128B, CU_TENSOR_MAP_FLOAT_OOB_FILL_NONE);
                if (r == CUDA_SUCCESS &&
                    cudaFuncSetAttribute(gemm_tf,
                                         cudaFuncAttributeMaxDynamicSharedMemorySize,
                                         SMEM_TMA) == cudaSuccess)
                    tc_ok = true;
            }
        }
    }

    weights_kernel<<<1, 512>>>(ape);

    if (tc_ok) {
        convXtf<<<65536, 256>>>((const float4*)x);
        convWtf<<<8192, 256>>>(Wkv, Wg);
        gemm_tf<<<dim3(16, 128), 256, SMEM_TMA>>>(mX, mW);
    } else {
        convX_kernel<<<65536, 256>>>((const float4*)x);
        convW_kernel<<<8192, 256>>>(Wkv, Wg);
        cudaFuncSetAttribute(gemm_mma, cudaFuncAttributeMaxDynamicSharedMemorySize, SMEM_CPA);
        gemm_mma<<<dim3(16, 128), 256, SMEM_CPA>>>();
    }

    combine_kernel<<<dim3(C_DIM, B_DIM), 512>>>(cosb, sinb, nw, out);
}

// round 9
// speedup vs baseline: 7.1334x; 1.0824x over previous
#include <cuda.h>
#include <cuda_runtime.h>
#include <cuda_bf16.h>
#include <cstdint>

// ---------------------------------------------------------------------------
// Problem constants
// ---------------------------------------------------------------------------
#define B_DIM   4
#define S_DIM   4096
#define H_DIM   4096
#define HD      512
#define ROPE_D  64
#define RATIO   4
#define C_DIM   (S_DIM / RATIO)          // 1024
#define M_TOT   (B_DIM * S_DIM)          // 16384
#define K_TOT   H_DIM                    // 4096
#define N_KV    (2 * HD)                 // 1024

// ---------------------------------------------------------------------------
// Device scratch
// ---------------------------------------------------------------------------
__device__ __align__(16) float           g_kvg[(size_t)M_TOT * N_KV];   // 64 MiB
__device__ __align__(16) float           g_w8[8 * HD];
__device__ __align__(16) float           g_w0[4 * HD];
// tf32 path: W pre-rounded (rna); X consumed raw (hw truncation)
__device__ __align__(1024) float         g_Wtf[(size_t)2048 * K_TOT];   // 32 MiB
// bf16 path (fallback)
__device__ __align__(1024) __nv_bfloat16 g_Xhi[(size_t)M_TOT * K_TOT];
__device__ __align__(1024) __nv_bfloat16 g_Xlo[(size_t)M_TOT * K_TOT];
__device__ __align__(1024) __nv_bfloat16 g_Whi[(size_t)2048 * K_TOT];
__device__ __align__(1024) __nv_bfloat16 g_Wlo[(size_t)2048 * K_TOT];

// ---------------------------------------------------------------------------
// PTX helpers (plain sm_90-level features only; no 'a'-suffix instructions)
// ---------------------------------------------------------------------------
__device__ __forceinline__ uint32_t smem_u32(const void* p) {
    uint32_t a;
    asm("{ .reg .u64 t; cvta.to.shared.u64 t, %1; cvt.u32.u64 %0, t; }"
        : "=r"(a) : "l"(p));
    return a;
}
__device__ __forceinline__ uint32_t tf32r(float f) {
    uint32_t r;
    asm("cvt.rna.tf32.f32 %0, %1;" : "=r"(r) : "f"(f));
    return r;
}

#define CP16(s, g) \
    asm volatile("cp.async.cg.shared.global [%0], [%1], 16;" :: "r"(s), "l"(g))
#define CP_COMMIT()  asm volatile("cp.async.commit_group;" ::: "memory")
#define CP_WAIT1()   asm volatile("cp.async.wait_group 1;" ::: "memory")
#define CP_WAIT0()   asm volatile("cp.async.wait_group 0;" ::: "memory")

#define LDSM4(r, addr) \
    asm volatile("ldmatrix.sync.aligned.m8n8.x4.shared.b16 {%0,%1,%2,%3}, [%4];" \
                 : "=r"((r)[0]), "=r"((r)[1]), "=r"((r)[2]), "=r"((r)[3]) : "r"(addr))

#define MMA16816(d, a, b0, b1) \
    asm volatile("mma.sync.aligned.m16n8k16.row.col.f32.bf16.bf16.f32 " \
                 "{%0,%1,%2,%3}, {%4,%5,%6,%7}, {%8,%9}, {%0,%1,%2,%3};" \
                 : "+f"((d)[0]), "+f"((d)[1]), "+f"((d)[2]), "+f"((d)[3]) \
                 : "r"((a)[0]), "r"((a)[1]), "r"((a)[2]), "r"((a)[3]), \
                   "r"(b0), "r"(b1))

#define MMATF32(d, a, b0, b1) \
    asm volatile("mma.sync.aligned.m16n8k8.row.col.f32.tf32.tf32.f32 " \
                 "{%0,%1,%2,%3}, {%4,%5,%6,%7}, {%8,%9}, {%0,%1,%2,%3};" \
                 : "+f"((d)[0]), "+f"((d)[1]), "+f"((d)[2]), "+f"((d)[3]) \
                 : "r"((a)[0]), "r"((a)[1]), "r"((a)[2]), "r"((a)[3]), \
                   "r"(b0), "r"(b1))

#define MBARRIER_INIT(addr, cnt) \
    asm volatile("mbarrier.init.shared.b64 [%0], %1;" :: "r"((uint32_t)(addr)), "r"((uint32_t)(cnt)) : "memory")
#define MBARRIER_ARRIVE(addr) \
    asm volatile("mbarrier.arrive.shared.b64 _, [%0];" :: "r"((uint32_t)(addr)) : "memory")
#define MBARRIER_EXPECT_TX(addr, bytes) \
    asm volatile("mbarrier.arrive.expect_tx.shared.b64 _, [%0], %1;" :: "r"((uint32_t)(addr)), "r"((uint32_t)(bytes)) : "memory")
#define MBARRIER_WAIT_PARITY(addr, parity) do {                                   \
    uint32_t _mb = (uint32_t)(addr);                                              \
    uint32_t _ph = (uint32_t)(parity);                                            \
    asm volatile(                                                                 \
        "{\n\t.reg .pred P1;\n\t"                                                 \
        "WAIT_LOOP_%=:\n\t"                                                       \
        "mbarrier.try_wait.parity.acquire.cta.shared::cta.b64 P1, [%0], %1, 0x989680;\n\t" \
        "@P1 bra.uni WAIT_DONE_%=;\n\t"                                           \
        "bra.uni WAIT_LOOP_%=;\n\t"                                               \
        "WAIT_DONE_%=:\n\t}"                                                      \
        :: "r"(_mb), "r"(_ph) : "memory");                                        \
} while (0)

#define TMA2D(smem_addr, map_ptr, cx, cy, mbar) \
    asm volatile("cp.async.bulk.tensor.2d.shared::cta.global.tile.mbarrier::complete_tx::bytes " \
                 "[%0], [%1, {%2, %3}], [%4];"                                    \
                 :: "r"((uint32_t)(smem_addr)), "l"(map_ptr),                     \
                    "r"((int32_t)(cx)), "r"((int32_t)(cy)),                       \
                    "r"((uint32_t)(mbar)) : "memory")

// ---------------------------------------------------------------------------
// Kernel: ape -> softmax weight tables
// ---------------------------------------------------------------------------
__global__ void weights_kernel(const float* __restrict__ ape) {
    int d = threadIdx.x;  // 0..511
    float v[8];
#pragma unroll
    for (int r = 0; r < 4; r++) {
        v[r]     = ape[r * 1024 + d];
        v[4 + r] = ape[r * 1024 + 512 + d];
    }
    float m4 = v[0];
#pragma unroll
    for (int i = 1; i < 4; i++) m4 = fmaxf(m4, v[i]);
    float e4[4]; float s4 = 0.f;
#pragma unroll
    for (int i = 0; i < 4; i++) { e4[i] = expf(v[i] - m4); s4 += e4[i]; }
    float inv4 = 1.f / s4;
#pragma unroll
    for (int i = 0; i < 4; i++) g_w0[i * HD + d] = e4[i] * inv4;
    float m8 = v[0];
#pragma unroll
    for (int i = 1; i < 8; i++) m8 = fmaxf(m8, v[i]);
    float e8[8]; float s8 = 0.f;
#pragma unroll
    for (int i = 0; i < 8; i++) { e8[i] = expf(v[i] - m8); s8 += e8[i]; }
    float inv8 = 1.f / s8;
#pragma unroll
    for (int i = 0; i < 8; i++) g_w8[i * HD + d] = e8[i] * inv8;
}

// ---------------------------------------------------------------------------
// tf32 W conversion (rna) — X is consumed raw via TMA (hw truncation)
// ---------------------------------------------------------------------------
__global__ void __launch_bounds__(256) convWtf(const float* __restrict__ wkv,
                                               const float* __restrict__ wg) {
    size_t i = (size_t)blockIdx.x * 256 + threadIdx.x;   // 2,097,152 float4
    size_t e0 = i * 4;
    size_t row = e0 >> 12;
    size_t k = e0 & 4095;
    const float* src = (row < 1024) ? (wkv + row * 4096 + k)
                                    : (wg + (row - 1024) * 4096 + k);
    float4 v = *reinterpret_cast<const float4*>(src);
    uint4 o;
    o.x = tf32r(v.x); o.y = tf32r(v.y); o.z = tf32r(v.z); o.w = tf32r(v.w);
    reinterpret_cast<uint4*>(g_Wtf)[i] = o;
}

// ---------------------------------------------------------------------------
// bf16 conversion kernels (fallback path)
// ---------------------------------------------------------------------------
__device__ __forceinline__ unsigned pk_bf2(float a, float b, float& ra, float& rb) {
    __nv_bfloat16 ha = __float2bfloat16_rn(a);
    __nv_bfloat16 hb = __float2bfloat16_rn(b);
    ra = a - __bfloat162float(ha);
    rb = b - __bfloat162float(hb);
    __nv_bfloat162 t(ha, hb);
    return *reinterpret_cast<unsigned*>(&t);
}
__device__ __forceinline__ unsigned pk_lo(float a, float b) {
    __nv_bfloat162 t(__float2bfloat16_rn(a), __float2bfloat16_rn(b));
    return *reinterpret_cast<unsigned*>(&t);
}

__global__ void __launch_bounds__(256) convX_kernel(const float4* __restrict__ x) {
    size_t i = (size_t)blockIdx.x * 256 + threadIdx.x;
    float4 v = x[i];
    float rx, ry, rz, rw;
    uint2 H, L;
    H.x = pk_bf2(v.x, v.y, rx, ry);
    H.y = pk_bf2(v.z, v.w, rz, rw);
    L.x = pk_lo(rx, ry);
    L.y = pk_lo(rz, rw);
    reinterpret_cast<uint2*>(g_Xhi)[i] = H;
    reinterpret_cast<uint2*>(g_Xlo)[i] = L;
}

__global__ void __launch_bounds__(256) convW_kernel(const float* __restrict__ wkv,
                                                    const float* __restrict__ wg) {
    size_t i = (size_t)blockIdx.x * 256 + threadIdx.x;
    size_t e0 = i * 4;
    size_t row = e0 >> 12;
    size_t k = e0 & 4095;
    const float* src = (row < 1024) ? (wkv + row * 4096 + k)
                                    : (wg + (row - 1024) * 4096 + k);
    float4 v = *reinterpret_cast<const float4*>(src);
    float rx, ry, rz, rw;
    uint2 H, L;
    H.x = pk_bf2(v.x, v.y, rx, ry);
    H.y = pk_bf2(v.z, v.w, rz, rw);
    L.x = pk_lo(rx, ry);
    L.y = pk_lo(rz, rw);
    reinterpret_cast<uint2*>(g_Whi)[i] = H;
    reinterpret_cast<uint2*>(g_Wlo)[i] = L;
}

// ---------------------------------------------------------------------------
// tf32 TMA GEMM (primary): CTA = 128 M x (64 kv + 64 gate), K in 128 chunks
// of 32. Stage (32 KB): A[128 rows x 128 B] + B[128 rows x 128 B]
// (B rows 0-63 kv, 64-127 gate). SW128: phys 16B-chunk = c ^ (row & 7).
// A is TMA'd directly from the fp32 input (hw tf32 truncation in the MMA).
// ---------------------------------------------------------------------------
#define NST      3
#define STG      32768
#define CHUNKS   128
#define SMEM_TMA (2048 + NST * STG)
#define SMEM_CPA (NST * STG)

__device__ __forceinline__ void issue_stage_tf(
    uint32_t st, int c, int m0, int n0, uint32_t fullb,
    const CUtensorMap* mX, const CUtensorMap* mW)
{
    const int k0 = c * 32;
    MBARRIER_EXPECT_TX(fullb, STG);
    TMA2D(st +     0, mX, k0, m0,        fullb);   // A: 128 rows x 128 B
    TMA2D(st + 16384, mW, k0, n0,        fullb);   // B kv: 64 rows
    TMA2D(st + 24576, mW, k0, 1024 + n0, fullb);   // B gate: 64 rows
}

__global__ void __launch_bounds__(256, 2) gemm_tf(
    const __grid_constant__ CUtensorMap mX,
    const __grid_constant__ CUtensorMap mW)
{
    extern __shared__ char ds[];
    const uint32_t raw  = smem_u32(ds);
    const uint32_t base = (raw + 1023u) & ~1023u;
    const uint32_t stage0 = base + 1024;
    const int t = threadIdx.x;
    const int m0 = blockIdx.y * 128;
    const int n0 = blockIdx.x * 64;

    const uint32_t FULLB  = base;
    const uint32_t EMPTYB = base + 24;

    if (t == 0) {
#pragma unroll
        for (int s = 0; s < 3; s++) {
            MBARRIER_INIT(FULLB + 8 * s, 1);
            MBARRIER_INIT(EMPTYB + 8 * s, 256);
        }
    }
    __syncthreads();

    if (t == 0) {
#pragma unroll
        for (int s = 0; s < 3; s++)
            issue_stage_tf(stage0 + s * STG, s, m0, n0, FULLB + 8 * s, &mX, &mW);
    }

    // compute setup (b16-view fragment mapping)
    const int lane = t & 31;
    const int wid = t >> 5;
    const int wm = wid & 1;        // m half (64 rows)
    const int wn = wid >> 1;       // n quarter (32 cols); 0,1 = kv; 2,3 = gate
    const int arow = (lane & 7) | (((lane >> 3) & 1) << 3);
    const int akh = (lane >> 4) & 1;
    const int brow = (lane & 7) | (((lane >> 4) & 1) << 3);
    const int bkh = (lane >> 3) & 1;
    const int rowAb = wm * 64 + arow;
    const int rowBb = wn * 32 + brow;
    const int sA = rowAb & 7;
    const int sB = rowBb & 7;

    float acc[4][4][4];
#pragma unroll
    for (int i = 0; i < 4; i++)
#pragma unroll
        for (int j = 0; j < 4; j++)
#pragma unroll
            for (int q = 0; q < 4; q++) acc[i][j][q] = 0.f;

    int slot = 0, ph = 0;
    for (int c = 0; c < CHUNKS; c++) {
        MBARRIER_WAIT_PARITY(FULLB + 8 * slot, ph);

        const uint32_t stA = stage0 + slot * STG;
        const uint32_t stB = stA + 16384;

#pragma unroll
        for (int ks = 0; ks < 4; ks++) {   // 4 x k8 per 32-K chunk
            uint32_t bb[2][4];
            const uint32_t pcA = (uint32_t)(((2 * ks + akh) ^ sA) << 4);
            const uint32_t pcB = (uint32_t)(((2 * ks + bkh) ^ sB) << 4);
#pragma unroll
            for (int q = 0; q < 2; q++) {
                const uint32_t ro = (uint32_t)(rowBb + q * 16) * 128 + pcB;
                LDSM4(bb[q], stB + ro);
            }
#pragma unroll
            for (int mf = 0; mf < 4; mf++) {
                uint32_t a[4];
                const uint32_t ro = (uint32_t)(rowAb + mf * 16) * 128 + pcA;
                LDSM4(a, stA + ro);
#pragma unroll
                for (int nf = 0; nf < 4; nf++) {
                    const int q = nf >> 1;
                    const int h = (nf & 1) * 2;
                    MMATF32(acc[mf][nf], a, bb[q][h], bb[q][h + 1]);
                }
            }
        }

        MBARRIER_ARRIVE(EMPTYB + 8 * slot);

        // rotate the issuing warp: each warp eats the skew wait 1/8 of chunks
        if (lane == 0 && wid == (c & 7) && c + 3 < CHUNKS) {
            MBARRIER_WAIT_PARITY(EMPTYB + 8 * slot, ph);
            issue_stage_tf(stA, c + 3, m0, n0, FULLB + 8 * slot, &mX, &mW);
        }

        if (++slot == 3) { slot = 0; ph ^= 1; }
    }

    __syncthreads();

    // epilogue: gate exchange + store
    float* sg = reinterpret_cast<float*>(ds + (base - raw) + 1024);  // [128][66]
    const int g  = lane >> 2;
    const int tg = lane & 3;

    if (wn >= 2) {
        const int cb = (wn - 2) * 32;
#pragma unroll
        for (int mf = 0; mf < 4; mf++) {
#pragma unroll
            for (int nf = 0; nf < 4; nf++) {
                const int row0 = wm * 64 + mf * 16 + g;
                const int col = cb + nf * 8 + tg * 2;
                sg[row0 * 66 + col]           = 1.f / (1.f + __expf(-acc[mf][nf][0]));
                sg[row0 * 66 + col + 1]       = 1.f / (1.f + __expf(-acc[mf][nf][1]));
                sg[(row0 + 8) * 66 + col]     = 1.f / (1.f + __expf(-acc[mf][nf][2]));
                sg[(row0 + 8) * 66 + col + 1] = 1.f / (1.f + __expf(-acc[mf][nf][3]));
            }
        }
    }
    __syncthreads();
    if (wn < 2) {
        const int cb = wn * 32;
#pragma unroll
        for (int mf = 0; mf < 4; mf++) {
#pragma unroll
            for (int nf = 0; nf < 4; nf++) {
                const int row0 = wm * 64 + mf * 16 + g;
                const int colw = cb + nf * 8 + tg * 2;
                float2 v0, v1;
                v0.x = acc[mf][nf][0] * sg[row0 * 66 + colw];
                v0.y = acc[mf][nf][1] * sg[row0 * 66 + colw + 1];
                v1.x = acc[mf][nf][2] * sg[(row0 + 8) * 66 + colw];
                v1.y = acc[mf][nf][3] * sg[(row0 + 8) * 66 + colw + 1];
                *reinterpret_cast<float2*>(&g_kvg[(size_t)(m0 + row0) * N_KV + n0 + colw]) = v0;
                *reinterpret_cast<float2*>(&g_kvg[(size_t)(m0 + row0 + 8) * N_KV + n0 + colw]) = v1;
            }
        }
    }
}

// ---------------------------------------------------------------------------
// bf16 cp.async GEMM (fallback, R4-validated)
// ---------------------------------------------------------------------------
__global__ void __launch_bounds__(256, 2) gemm_mma() {
    extern __shared__ char ds[];
    const uint32_t sb = smem_u32(ds);
    const int t = threadIdx.x;
    const int m0 = blockIdx.y * 128;
    const int n0 = blockIdx.x * 64;

    const int lr = t >> 2;
    const int lc = t & 3;
    const __nv_bfloat16* pAh  = g_Xhi + (size_t)(m0 + lr) * 4096 + lc * 8;
    const __nv_bfloat16* pAl  = g_Xlo + (size_t)(m0 + lr) * 4096 + lc * 8;
    const __nv_bfloat16* pBhk = g_Whi + (size_t)(n0 + lr) * 4096 + lc * 8;
    const __nv_bfloat16* pBhg = g_Whi + (size_t)(1024 + n0 + lr) * 4096 + lc * 8;
    const __nv_bfloat16* pBlk = g_Wlo + (size_t)(n0 + lr) * 4096 + lc * 8;
    const __nv_bfloat16* pBlg = g_Wlo + (size_t)(1024 + n0 + lr) * 4096 + lc * 8;
    const uint32_t da = lr * 64 + ((lc ^ ((lr >> 1) & 3)) << 4);
    const size_t AROW64 = (size_t)64 * 4096;

    const int lane = t & 31;
    const int wid = t >> 5;
    const int wm = wid & 1;
    const int wn = wid >> 1;
    const int arow = (lane & 7) | (((lane >> 3) & 1) << 3);
    const int akh = (lane >> 4) & 1;
    const int brow = (lane & 7) | (((lane >> 4) & 1) << 3);
    const int bkh = (lane >> 3) & 1;
    const int rowAb = wm * 64 + arow;
    const int rowBb = wn * 32 + brow;
    const int sA = (rowAb >> 1) & 3;
    const int sB = (rowBb >> 1) & 3;

    float acc[4][4][4];
#pragma unroll
    for (int i = 0; i < 4; i++)
#pragma unroll
        for (int j = 0; j < 4; j++)
#pragma unroll
            for (int q = 0; q < 4; q++) acc[i][j][q] = 0.f;

#pragma unroll
    for (int s = 0; s < 2; s++) {
        const uint32_t st = sb + s * STG;
        const size_t k = (size_t)s * 32;
        CP16(st + da,               pAh + k);
        CP16(st + da + 4096,        pAh + k + AROW64);
        CP16(st + 8192 + da,        pAl + k);
        CP16(st + 8192 + da + 4096, pAl + k + AROW64);
        CP16(st + 16384 + da,        pBhk + k);
        CP16(st + 16384 + da + 4096, pBhg + k);
        CP16(st + 24576 + da,        pBlk + k);
        CP16(st + 24576 + da + 4096, pBlg + k);
        CP_COMMIT();
    }

    int slot = 0, wslot = 2;
    for (int c = 0; c < CHUNKS; c++) {
        CP_WAIT1();
        __syncthreads();
        if (c + 2 < CHUNKS) {
            const uint32_t st = sb + wslot * STG;
            const size_t k = (size_t)(c + 2) * 32;
            CP16(st + da,               pAh + k);
            CP16(st + da + 4096,        pAh + k + AROW64);
            CP16(st + 8192 + da,        pAl + k);
            CP16(st + 8192 + da + 4096, pAl + k + AROW64);
            CP16(st + 16384 + da,        pBhk + k);
            CP16(st + 16384 + da + 4096, pBhg + k);
            CP16(st + 24576 + da,        pBlk + k);
            CP16(st + 24576 + da + 4096, pBlg + k);
        }
        CP_COMMIT();

        const uint32_t st = sb + slot * STG;
        const uint32_t stAh = st;
        const uint32_t stAl = st + 8192;
        const uint32_t stBh = st + 16384;
        const uint32_t stBl = st + 24576;

#pragma unroll
        for (int ks = 0; ks < 2; ks++) {
            uint32_t bh[2][4], bl[2][4];
            const uint32_t pcA = (uint32_t)(((ks * 2 + akh) ^ sA) << 4);
            const uint32_t pcB = (uint32_t)(((ks * 2 + bkh) ^ sB) << 4);
#pragma unroll
            for (int q = 0; q < 2; q++) {
                const uint32_t ro = (uint32_t)(rowBb + q * 16) * 64 + pcB;
                LDSM4(bh[q], stBh + ro);
                LDSM4(bl[q], stBl + ro);
            }
#pragma unroll
            for (int mf = 0; mf < 4; mf++) {
                uint32_t ah[4], al[4];
                const uint32_t ro = (uint32_t)(rowAb + mf * 16) * 64 + pcA;
                LDSM4(ah, stAh + ro);
                LDSM4(al, stAl + ro);
#pragma unroll
                for (int nf = 0; nf < 4; nf++) {
                    const int q = nf >> 1;
                    const int h = (nf & 1) * 2;
                    MMA16816(acc[mf][nf], ah, bh[q][h], bh[q][h + 1]);
                    MMA16816(acc[mf][nf], ah, bl[q][h], bl[q][h + 1]);
                    MMA16816(acc[mf][nf], al, bh[q][h], bh[q][h + 1]);
                }
            }
        }
        slot = (slot == 2) ? 0 : slot + 1;
        wslot = (wslot == 2) ? 0 : wslot + 1;
    }

    CP_WAIT0();
    __syncthreads();

    float* sg = reinterpret_cast<float*>(ds);
    const int g  = lane >> 2;
    const int tg = lane & 3;

    if (wn >= 2) {
        const int cb = (wn - 2) * 32;
#pragma unroll
        for (int mf = 0; mf < 4; mf++) {
#pragma unroll
            for (int nf = 0; nf < 4; nf++) {
                const int row0 = wm * 64 + mf * 16 + g;
                const int col = cb + nf * 8 + tg * 2;
                sg[row0 * 66 + col]           = 1.f / (1.f + __expf(-acc[mf][nf][0]));
                sg[row0 * 66 + col + 1]       = 1.f / (1.f + __expf(-acc[mf][nf][1]));
                sg[(row0 + 8) * 66 + col]     = 1.f / (1.f + __expf(-acc[mf][nf][2]));
                sg[(row0 + 8) * 66 + col + 1] = 1.f / (1.f + __expf(-acc[mf][nf][3]));
            }
        }
    }
    __syncthreads();
    if (wn < 2) {
        const int cb = wn * 32;
#pragma unroll
        for (int mf = 0; mf < 4; mf++) {
#pragma unroll
            for (int nf = 0; nf < 4; nf++) {
                const int row0 = wm * 64 + mf * 16 + g;
                const int colw = cb + nf * 8 + tg * 2;
                float2 v0, v1;
                v0.x = acc[mf][nf][0] * sg[row0 * 66 + colw];
                v0.y = acc[mf][nf][1] * sg[row0 * 66 + colw + 1];
                v1.x = acc[mf][nf][2] * sg[(row0 + 8) * 66 + colw];
                v1.y = acc[mf][nf][3] * sg[(row0 + 8) * 66 + colw + 1];
                *reinterpret_cast<float2*>(&g_kvg[(size_t)(m0 + row0) * N_KV + n0 + colw]) = v0;
                *reinterpret_cast<float2*>(&g_kvg[(size_t)(m0 + row0 + 8) * N_KV + n0 + colw]) = v1;
            }
        }
    }
}

// ---------------------------------------------------------------------------
// Combine + RMSNorm + partial RoPE (validated R1)
// ---------------------------------------------------------------------------
__global__ void __launch_bounds__(512) combine_kernel(const float* __restrict__ cosb,
                                                      const float* __restrict__ sinb,
                                                      const float* __restrict__ nw,
                                                      float* __restrict__ out) {
    __shared__ float sh[512];
    __shared__ float wsum[16];
    __shared__ float s_rstd;

    const int d = threadIdx.x;
    const int c = blockIdx.x;
    const int b = blockIdx.y;

    const size_t base = ((size_t)b * S_DIM + (size_t)c * RATIO) * (size_t)N_KV;

    float tacc = 0.f;
    if (c == 0) {
#pragma unroll
        for (int r = 0; r < 4; r++)
            tacc += g_kvg[base + (size_t)r * N_KV + d] * g_w0[r * HD + d];
    } else {
#pragma unroll
        for (int r = 0; r < 4; r++)
            tacc += g_kvg[base + (size_t)r * N_KV + d] * g_w8[r * HD + d];
        const size_t basep = base - (size_t)RATIO * N_KV;
#pragma unroll
        for (int r = 0; r < 4; r++)
            tacc += g_kvg[basep + (size_t)r * N_KV + HD + d] * g_w8[(4 + r) * HD + d];
    }
    sh[d] = tacc;

    float v = tacc * tacc;
#pragma unroll
    for (int off = 16; off; off >>= 1) v += __shfl_xor_sync(0xffffffffu, v, off);
    if ((d & 31) == 0) wsum[d >> 5] = v;
    __syncthreads();
    if (d == 0) {
        float s = 0.f;
#pragma unroll
        for (int w = 0; w < 16; w++) s += wsum[w];
        s_rstd = rsqrtf(s * (1.f / (float)HD) + 1e-6f);
    }
    __syncthreads();
    const float rstd = s_rstd;

    float o;
    if (d < HD - ROPE_D) {
        o = sh[d] * rstd * nw[d];
    } else {
        const int p  = (d - (HD - ROPE_D)) >> 1;
        const int de = (HD - ROPE_D) + 2 * p;
        const int dq = de + 1;
        const float e  = sh[de] * rstd * nw[de];
        const float oo = sh[dq] * rstd * nw[dq];
        const size_t ci = ((size_t)b * C_DIM + c) * (ROPE_D / 2) + p;
        const float cv = cosb[ci];
        const float sv = sinb[ci];
        o = ((d & 1) == 0) ? (e * cv - oo * sv) : (e * sv + oo * cv);
    }
    out[((size_t)b * C_DIM + c) * HD + d] = o;
}

// ---------------------------------------------------------------------------
// Launch
// ---------------------------------------------------------------------------
typedef CUresult (CUDAAPI *PFN_tmEncode)(
    CUtensorMap*, CUtensorMapDataType, cuuint32_t, void*,
    const cuuint64_t*, const cuuint64_t*, const cuuint32_t*, const cuuint32_t*,
    CUtensorMapInterleave, CUtensorMapSwizzle, CUtensorMapL2promotion,
    CUtensorMapFloatOOBfill);

extern "C" void kernel_launch(void* const* d_in, const int* in_sizes, int n_in,
                              void* d_out, int out_size) {
    const float* x    = (const float*)d_in[0];
    const float* cosb = (const float*)d_in[1];
    const float* sinb = (const float*)d_in[2];
    const float* Wkv  = (const float*)d_in[3];
    const float* Wg   = (const float*)d_in[4];
    const float* ape  = (const float*)d_in[5];
    const float* nw   = (const float*)d_in[6];
    float* out = (float*)d_out;

    bool tc_ok = false;
    CUtensorMap mX{}, mW{};
    {
        void* fp = nullptr;
        cudaDriverEntryPointQueryResult qr;
        PFN_tmEncode enc = nullptr;
        if (cudaGetDriverEntryPoint("cuTensorMapEncodeTiled", &fp,
                                    cudaEnableDefault, &qr) == cudaSuccess && fp)
            enc = (PFN_tmEncode)fp;
        if (enc) {
            void* pw = nullptr;
            cudaGetSymbolAddress(&pw, g_Wtf);
            if (pw) {
                cuuint64_t dX[2] = {K_TOT, M_TOT};
                cuuint64_t sX[1] = {K_TOT * 4};
                cuuint64_t dW[2] = {K_TOT, 2048};
                cuuint64_t sW[1] = {K_TOT * 4};
                cuuint32_t boxX[2] = {32, 128};
                cuuint32_t boxW[2] = {32, 64};
                cuuint32_t es[2]  = {1, 1};
                CUresult r;
                r = enc(&mX, CU_TENSOR_MAP_DATA_TYPE_FLOAT32, 2, (void*)x, dX, sX, boxX, es,
                        CU_TENSOR_MAP_INTERLEAVE_NONE, CU_TENSOR_MAP_SWIZZLE_128B,
                        CU_TENSOR_MAP_L2_PROMOTION_L2_128B, CU_TENSOR_MAP_FLOAT_OOB_FILL_NONE);
                if (r == CUDA_SUCCESS)
                    r = enc(&mW, CU_TENSOR_MAP_DATA_TYPE_FLOAT32, 2, pw, dW, sW, boxW, es,
                            CU_TENSOR_MAP_INTERLEAVE_NONE, CU_TENSOR_MAP_SWIZZLE_128B,
                            CU_TENSOR_MAP_L2_PROMOTION_L2_128B, CU_TENSOR_MAP_FLOAT_OOB_FILL_NONE);
                if (r == CUDA_SUCCESS &&
                    cudaFuncSetAttribute(gemm_tf,
                                         cudaFuncAttributeMaxDynamicSharedMemorySize,
                                         SMEM_TMA) == cudaSuccess)
                    tc_ok = true;
            }
        }
    }

    weights_kernel<<<1, 512>>>(ape);

    if (tc_ok) {
        convWtf<<<8192, 256>>>(Wkv, Wg);
        gemm_tf<<<dim3(16, 128), 256, SMEM_TMA>>>(mX, mW);
    } else {
        convX_kernel<<<65536, 256>>>((const float4*)x);
        convW_kernel<<<8192, 256>>>(Wkv, Wg);
        cudaFuncSetAttribute(gemm_mma, cudaFuncAttributeMaxDynamicSharedMemorySize, SMEM_CPA);
        gemm_mma<<<dim3(16, 128), 256, SMEM_CPA>>>();
    }

    combine_kernel<<<dim3(C_DIM, B_DIM), 512>>>(cosb, sinb, nw, out);
}